// round 1
// baseline (speedup 1.0000x reference)
#include <cuda_runtime.h>
#include <cuda_bf16.h>
#include <math.h>

// Problem constants
#define BATCH 4
#define SEQ   2048
#define EMB   1024
#define HEADS 16
#define HDIM  64          // EMB / HEADS
#define M_ROWS (BATCH*SEQ) // 8192

// Scratch (device globals — allocation-free per harness rules)
__device__ float g_qkv[(size_t)M_ROWS * 3 * EMB];   // [B*S, 3E]  ~100.7 MB
__device__ float g_attn[(size_t)M_ROWS * EMB];      // [B*S, E]   ~33.6 MB

// ---------------------------------------------------------------------------
// Tiled SGEMM with bias: C[M,N] = A[M,K] @ B[K,N] + bias[N]
// BM=BN=128, BK=16, 256 threads, 8x8 per-thread microtile.
// M % 128 == 0, N % 128 == 0, K % 16 == 0 (holds for all our shapes).
// ---------------------------------------------------------------------------
#define BM 128
#define BN 128
#define BK 16
#define TM 8
#define TN 8

__global__ __launch_bounds__(256)
void sgemm_bias(const float* __restrict__ A, const float* __restrict__ B,
                const float* __restrict__ bias, float* __restrict__ C,
                int M, int N, int K)
{
    __shared__ float As[BK][BM];   // A tile stored transposed
    __shared__ float Bs[BK][BN];

    const int bx = blockIdx.x;     // N tile
    const int by = blockIdx.y;     // M tile
    const int tid = threadIdx.x;
    const int tcol = tid & 15;     // 0..15
    const int trow = tid >> 4;     // 0..15

    const float* Ab = A + (size_t)by * BM * K;
    const float* Bb = B + (size_t)bx * BN;

    float acc[TM][TN];
    #pragma unroll
    for (int i = 0; i < TM; ++i)
        #pragma unroll
        for (int j = 0; j < TN; ++j) acc[i][j] = 0.f;

    for (int k0 = 0; k0 < K; k0 += BK) {
        // Load A tile: 128x16 floats = 512 float4; 2 per thread
        #pragma unroll
        for (int i = 0; i < 2; ++i) {
            int idx = tid + i * 256;          // 0..511
            int r = idx >> 2;                 // 0..127
            int c = (idx & 3) << 2;           // 0,4,8,12
            float4 v = *reinterpret_cast<const float4*>(Ab + (size_t)r * K + k0 + c);
            As[c + 0][r] = v.x; As[c + 1][r] = v.y;
            As[c + 2][r] = v.z; As[c + 3][r] = v.w;
        }
        // Load B tile: 16x128 floats = 512 float4; 2 per thread
        #pragma unroll
        for (int i = 0; i < 2; ++i) {
            int idx = tid + i * 256;
            int r = idx >> 5;                 // 0..15
            int c = (idx & 31) << 2;          // 0..124
            *reinterpret_cast<float4*>(&Bs[r][c]) =
                *reinterpret_cast<const float4*>(Bb + (size_t)(k0 + r) * N + c);
        }
        __syncthreads();

        #pragma unroll
        for (int kk = 0; kk < BK; ++kk) {
            float ra[TM], rb[TN];
            #pragma unroll
            for (int i = 0; i < TM; ++i) ra[i] = As[kk][trow * TM + i];
            #pragma unroll
            for (int j = 0; j < TN; ++j) rb[j] = Bs[kk][tcol * TN + j];
            #pragma unroll
            for (int i = 0; i < TM; ++i)
                #pragma unroll
                for (int j = 0; j < TN; ++j)
                    acc[i][j] += ra[i] * rb[j];
        }
        __syncthreads();
    }

    // Epilogue: add bias, store
    #pragma unroll
    for (int i = 0; i < TM; ++i) {
        int row = by * BM + trow * TM + i;
        #pragma unroll
        for (int j = 0; j < TN; j += 4) {
            int col = bx * BN + tcol * TN + j;
            float4 b4 = *reinterpret_cast<const float4*>(bias + col);
            float4 o;
            o.x = acc[i][j + 0] + b4.x;
            o.y = acc[i][j + 1] + b4.y;
            o.z = acc[i][j + 2] + b4.z;
            o.w = acc[i][j + 3] + b4.w;
            *reinterpret_cast<float4*>(C + (size_t)row * N + col) = o;
        }
    }
}

// ---------------------------------------------------------------------------
// Causal flash attention over packed QKV buffer.
// Layout: g_qkv[b*S + s][0:E]=Q, [E:2E]=K, [2E:3E]=V; head h -> cols h*64..
// Block: 128 threads, one query row per thread (128-row query tile).
// Grid: (S/128, H, B). K/V processed in 32-row SMEM tiles, online softmax.
// ---------------------------------------------------------------------------
__global__ __launch_bounds__(128, 1)
void attn_kernel(float* __restrict__ out)
{
    const int b  = blockIdx.z;
    const int h  = blockIdx.y;
    const int qt = blockIdx.x;
    const int tid = threadIdx.x;
    const int qrow = qt * 128 + tid;
    const float scale = 0.125f;   // 1/sqrt(64)

    const size_t row3E = (size_t)3 * EMB;
    const float* basep = g_qkv + (size_t)b * SEQ * row3E;

    // Q row in registers (pre-scaled)
    float q[HDIM];
    {
        const float* qp = basep + (size_t)qrow * row3E + h * HDIM;
        #pragma unroll
        for (int d = 0; d < HDIM; d += 4) {
            float4 v = *reinterpret_cast<const float4*>(qp + d);
            q[d + 0] = v.x * scale; q[d + 1] = v.y * scale;
            q[d + 2] = v.z * scale; q[d + 3] = v.w * scale;
        }
    }

    float m = -INFINITY, l = 0.f;
    float acc[HDIM];
    #pragma unroll
    for (int d = 0; d < HDIM; ++d) acc[d] = 0.f;

    __shared__ float Ks[32][HDIM];
    __shared__ float Vs[32][HDIM];

    const int kend = qt * 128 + 128;   // exclusive
    for (int k0 = 0; k0 < kend; k0 += 32) {
        __syncthreads();
        // Cooperative K/V tile load: 32x64 floats each -> 4 float4 per thread each
        #pragma unroll
        for (int i = 0; i < 4; ++i) {
            int idx = tid + i * 128;       // float4 index 0..511
            int r = idx >> 4;              // 0..31
            int c = (idx & 15) << 2;       // 0..60
            const float* rowp = basep + (size_t)(k0 + r) * row3E + h * HDIM + c;
            *reinterpret_cast<float4*>(&Ks[r][c]) =
                *reinterpret_cast<const float4*>(rowp + EMB);
            *reinterpret_cast<float4*>(&Vs[r][c]) =
                *reinterpret_cast<const float4*>(rowp + 2 * EMB);
        }
        __syncthreads();

        // Scores for 32 keys (4-way ILP)
        float s[32];
        #pragma unroll
        for (int j = 0; j < 32; j += 4) {
            float s0 = 0.f, s1 = 0.f, s2 = 0.f, s3 = 0.f;
            #pragma unroll
            for (int d = 0; d < HDIM; ++d) {
                float qd = q[d];
                s0 += qd * Ks[j + 0][d];
                s1 += qd * Ks[j + 1][d];
                s2 += qd * Ks[j + 2][d];
                s3 += qd * Ks[j + 3][d];
            }
            s[j] = s0; s[j + 1] = s1; s[j + 2] = s2; s[j + 3] = s3;
        }

        // Causal mask (only needed on diagonal tiles)
        if (k0 + 32 > qrow + 1) {
            #pragma unroll
            for (int j = 0; j < 32; ++j)
                if (k0 + j > qrow) s[j] = -INFINITY;
        }

        // Online softmax update
        float mt = m;
        #pragma unroll
        for (int j = 0; j < 32; ++j) mt = fmaxf(mt, s[j]);
        float corr = __expf(m - mt);
        m = mt;
        l *= corr;
        #pragma unroll
        for (int d = 0; d < HDIM; ++d) acc[d] *= corr;

        #pragma unroll
        for (int j = 0; j < 32; ++j) {
            float p = __expf(s[j] - m);
            l += p;
            #pragma unroll
            for (int d = 0; d < HDIM; ++d)
                acc[d] += p * Vs[j][d];
        }
    }

    const float inv = 1.f / l;
    float* op = out + ((size_t)b * SEQ + qrow) * EMB + h * HDIM;
    #pragma unroll
    for (int d = 0; d < HDIM; d += 4) {
        float4 o;
        o.x = acc[d + 0] * inv; o.y = acc[d + 1] * inv;
        o.z = acc[d + 2] * inv; o.w = acc[d + 3] * inv;
        *reinterpret_cast<float4*>(op + d) = o;
    }
}

// ---------------------------------------------------------------------------
// Launch
// ---------------------------------------------------------------------------
extern "C" void kernel_launch(void* const* d_in, const int* in_sizes, int n_in,
                              void* d_out, int out_size)
{
    (void)in_sizes; (void)n_in; (void)out_size;
    const float* x     = (const float*)d_in[0];   // [B,S,E]
    const float* W_qkv = (const float*)d_in[1];   // [E, 3E]
    const float* b_qkv = (const float*)d_in[2];   // [3E]
    const float* W_o   = (const float*)d_in[3];   // [E, E]
    const float* b_o   = (const float*)d_in[4];   // [E]
    float* out = (float*)d_out;                   // [B,S,E]

    float* qkv_ptr  = nullptr;
    float* attn_ptr = nullptr;
    cudaGetSymbolAddress((void**)&qkv_ptr,  g_qkv);
    cudaGetSymbolAddress((void**)&attn_ptr, g_attn);

    // 1) QKV projection: [8192,1024] @ [1024,3072] + b
    {
        dim3 grid(3 * EMB / BN, M_ROWS / BM);
        sgemm_bias<<<grid, 256>>>(x, W_qkv, b_qkv, qkv_ptr, M_ROWS, 3 * EMB, EMB);
    }

    // 2) Causal multi-head attention
    {
        dim3 grid(SEQ / 128, HEADS, BATCH);
        attn_kernel<<<grid, 128>>>(attn_ptr);
    }

    // 3) Output projection: [8192,1024] @ [1024,1024] + b
    {
        dim3 grid(EMB / BN, M_ROWS / BM);
        sgemm_bias<<<grid, 256>>>(attn_ptr, W_o, b_o, out, M_ROWS, EMB, EMB);
    }
}

// round 2
// speedup vs baseline: 1.8520x; 1.8520x over previous
#include <cuda_runtime.h>
#include <cuda_bf16.h>
#include <math.h>

// Problem constants
#define BATCH 4
#define SEQ   2048
#define EMB   1024
#define HEADS 16
#define HDIM  64
#define M_ROWS (BATCH*SEQ)   // 8192

typedef unsigned long long ull;

// Scratch (device globals — allocation-free per harness rules)
__device__ float g_qkv[(size_t)M_ROWS * 3 * EMB];   // [B*S, 3E]
__device__ float g_attn[(size_t)M_ROWS * EMB];      // [B*S, E]

// ---------------------------------------------------------------------------
// Helpers
// ---------------------------------------------------------------------------
__device__ __forceinline__ unsigned f2tf32(float x) {
    unsigned r;
    asm("cvt.rna.tf32.f32 %0, %1;" : "=r"(r) : "f"(x));
    return r;
}

__device__ __forceinline__ ull pk2(float lo, float hi) {
    ull r;
    asm("mov.b64 %0, {%1, %2};" : "=l"(r) : "f"(lo), "f"(hi));
    return r;
}
__device__ __forceinline__ void upk2(ull v, float& lo, float& hi) {
    asm("mov.b64 {%0, %1}, %2;" : "=f"(lo), "=f"(hi) : "l"(v));
}
__device__ __forceinline__ ull fma2(ull a, ull b, ull c) {
    ull d;
    asm("fma.rn.f32x2 %0, %1, %2, %3;" : "=l"(d) : "l"(a), "l"(b), "l"(c));
    return d;
}
__device__ __forceinline__ ull mul2(ull a, ull b) {
    ull d;
    asm("mul.rn.f32x2 %0, %1, %2;" : "=l"(d) : "l"(a), "l"(b));
    return d;
}

// ---------------------------------------------------------------------------
// tf32 tensor-core GEMM with bias: C[M,N] = A[M,K] @ B[K,N] + bias[N]
// Tile 128x128x16, 256 threads (8 warps, 2x4), warp tile 64x32.
// mma.sync.aligned.m16n8k8.row.col.f32.tf32.tf32.f32
// Requires M%128==0, N%128==0, K%16==0.
// ---------------------------------------------------------------------------
#define GBM 128
#define GBN 128
#define GBK 16
#define AST 20     // A smem row stride (floats): conflict-free fragment loads
#define BST 136    // B smem row stride

__global__ __launch_bounds__(256)
void gemm_tf32(const float* __restrict__ A, const float* __restrict__ B,
               const float* __restrict__ bias, float* __restrict__ C,
               int M, int N, int K)
{
    __shared__ __align__(16) float As[2][GBM][AST];   // [stage][m][k]
    __shared__ __align__(16) float Bs[2][GBK][BST];   // [stage][k][n]

    const int tid  = threadIdx.x;
    const int wid  = tid >> 5;
    const int lane = tid & 31;
    const int g = lane >> 2;   // group id 0..7
    const int t = lane & 3;    // thread-in-group 0..3

    const int bx = blockIdx.x;
    const int by = blockIdx.y;
    const int wm = (wid >> 2) * 64;   // warp m offset: 0 / 64
    const int wn = (wid & 3) * 32;    // warp n offset: 0/32/64/96

    const float* Ab = A + (size_t)by * GBM * K;
    const float* Bb = B + (size_t)bx * GBN;

    // per-thread load coordinates (2 float4 each for A and B)
    const int a_r0 = (tid + 0)   >> 2, a_c0 = ((tid + 0)   & 3) << 2;
    const int a_r1 = (tid + 256) >> 2, a_c1 = ((tid + 256) & 3) << 2;
    const int b_r0 = (tid + 0)   >> 5, b_c0 = ((tid + 0)   & 31) << 2;
    const int b_r1 = (tid + 256) >> 5, b_c1 = ((tid + 256) & 31) << 2;

    float acc[4][4][4];
    #pragma unroll
    for (int i = 0; i < 4; ++i)
        #pragma unroll
        for (int j = 0; j < 4; ++j)
            #pragma unroll
            for (int c = 0; c < 4; ++c) acc[i][j][c] = 0.f;

    float4 ra0, ra1, rb0, rb1;

    // prologue: load tile 0
    ra0 = *reinterpret_cast<const float4*>(Ab + (size_t)a_r0 * K + a_c0);
    ra1 = *reinterpret_cast<const float4*>(Ab + (size_t)a_r1 * K + a_c1);
    rb0 = *reinterpret_cast<const float4*>(Bb + (size_t)b_r0 * N + b_c0);
    rb1 = *reinterpret_cast<const float4*>(Bb + (size_t)b_r1 * N + b_c1);

    // store stage 0 (convert to tf32 bits)
    {
        float* ap0 = &As[0][a_r0][a_c0];
        ap0[0] = __uint_as_float(f2tf32(ra0.x)); ap0[1] = __uint_as_float(f2tf32(ra0.y));
        ap0[2] = __uint_as_float(f2tf32(ra0.z)); ap0[3] = __uint_as_float(f2tf32(ra0.w));
        float* ap1 = &As[0][a_r1][a_c1];
        ap1[0] = __uint_as_float(f2tf32(ra1.x)); ap1[1] = __uint_as_float(f2tf32(ra1.y));
        ap1[2] = __uint_as_float(f2tf32(ra1.z)); ap1[3] = __uint_as_float(f2tf32(ra1.w));
        float* bp0 = &Bs[0][b_r0][b_c0];
        bp0[0] = __uint_as_float(f2tf32(rb0.x)); bp0[1] = __uint_as_float(f2tf32(rb0.y));
        bp0[2] = __uint_as_float(f2tf32(rb0.z)); bp0[3] = __uint_as_float(f2tf32(rb0.w));
        float* bp1 = &Bs[0][b_r1][b_c1];
        bp1[0] = __uint_as_float(f2tf32(rb1.x)); bp1[1] = __uint_as_float(f2tf32(rb1.y));
        bp1[2] = __uint_as_float(f2tf32(rb1.z)); bp1[3] = __uint_as_float(f2tf32(rb1.w));
    }
    __syncthreads();

    const int ntiles = K / GBK;
    for (int kt = 0; kt < ntiles; ++kt) {
        const int st = kt & 1;

        // prefetch next tile (global loads early for latency hiding)
        if (kt + 1 < ntiles) {
            const int k0 = (kt + 1) * GBK;
            ra0 = *reinterpret_cast<const float4*>(Ab + (size_t)a_r0 * K + k0 + a_c0);
            ra1 = *reinterpret_cast<const float4*>(Ab + (size_t)a_r1 * K + k0 + a_c1);
            rb0 = *reinterpret_cast<const float4*>(Bb + (size_t)(k0 + b_r0) * N + b_c0);
            rb1 = *reinterpret_cast<const float4*>(Bb + (size_t)(k0 + b_r1) * N + b_c1);
        }

        // compute: two k-steps of 8
        #pragma unroll
        for (int ks = 0; ks < GBK; ks += 8) {
            unsigned a[4][4], b[4][2];
            #pragma unroll
            for (int mf = 0; mf < 4; ++mf) {
                const int mr = wm + mf * 16;
                a[mf][0] = __float_as_uint(As[st][mr + g    ][ks + t    ]);
                a[mf][1] = __float_as_uint(As[st][mr + g + 8][ks + t    ]);
                a[mf][2] = __float_as_uint(As[st][mr + g    ][ks + t + 4]);
                a[mf][3] = __float_as_uint(As[st][mr + g + 8][ks + t + 4]);
            }
            #pragma unroll
            for (int nf = 0; nf < 4; ++nf) {
                const int nc = wn + nf * 8 + g;
                b[nf][0] = __float_as_uint(Bs[st][ks + t    ][nc]);
                b[nf][1] = __float_as_uint(Bs[st][ks + t + 4][nc]);
            }
            #pragma unroll
            for (int mf = 0; mf < 4; ++mf)
                #pragma unroll
                for (int nf = 0; nf < 4; ++nf) {
                    asm volatile(
                        "mma.sync.aligned.m16n8k8.row.col.f32.tf32.tf32.f32 "
                        "{%0,%1,%2,%3}, {%4,%5,%6,%7}, {%8,%9}, {%0,%1,%2,%3};"
                        : "+f"(acc[mf][nf][0]), "+f"(acc[mf][nf][1]),
                          "+f"(acc[mf][nf][2]), "+f"(acc[mf][nf][3])
                        : "r"(a[mf][0]), "r"(a[mf][1]), "r"(a[mf][2]), "r"(a[mf][3]),
                          "r"(b[nf][0]), "r"(b[nf][1]));
                }
        }

        // store next stage
        if (kt + 1 < ntiles) {
            const int ns = st ^ 1;
            float* ap0 = &As[ns][a_r0][a_c0];
            ap0[0] = __uint_as_float(f2tf32(ra0.x)); ap0[1] = __uint_as_float(f2tf32(ra0.y));
            ap0[2] = __uint_as_float(f2tf32(ra0.z)); ap0[3] = __uint_as_float(f2tf32(ra0.w));
            float* ap1 = &As[ns][a_r1][a_c1];
            ap1[0] = __uint_as_float(f2tf32(ra1.x)); ap1[1] = __uint_as_float(f2tf32(ra1.y));
            ap1[2] = __uint_as_float(f2tf32(ra1.z)); ap1[3] = __uint_as_float(f2tf32(ra1.w));
            float* bp0 = &Bs[ns][b_r0][b_c0];
            bp0[0] = __uint_as_float(f2tf32(rb0.x)); bp0[1] = __uint_as_float(f2tf32(rb0.y));
            bp0[2] = __uint_as_float(f2tf32(rb0.z)); bp0[3] = __uint_as_float(f2tf32(rb0.w));
            float* bp1 = &Bs[ns][b_r1][b_c1];
            bp1[0] = __uint_as_float(f2tf32(rb1.x)); bp1[1] = __uint_as_float(f2tf32(rb1.y));
            bp1[2] = __uint_as_float(f2tf32(rb1.z)); bp1[3] = __uint_as_float(f2tf32(rb1.w));
            __syncthreads();
        }
    }

    // epilogue: bias + store (fp32 accum)
    #pragma unroll
    for (int mf = 0; mf < 4; ++mf) {
        const int row = by * GBM + wm + mf * 16 + g;
        #pragma unroll
        for (int nf = 0; nf < 4; ++nf) {
            const int col = bx * GBN + wn + nf * 8 + 2 * t;
            float2 b2 = *reinterpret_cast<const float2*>(bias + col);
            float2 o0 = make_float2(acc[mf][nf][0] + b2.x, acc[mf][nf][1] + b2.y);
            float2 o1 = make_float2(acc[mf][nf][2] + b2.x, acc[mf][nf][3] + b2.y);
            *reinterpret_cast<float2*>(C + (size_t)row * N + col)       = o0;
            *reinterpret_cast<float2*>(C + (size_t)(row + 8) * N + col) = o1;
        }
    }
}

// ---------------------------------------------------------------------------
// Causal flash attention with packed f32x2 math.
// One query row per thread, 128-thread blocks, 32-key SMEM tiles.
// ---------------------------------------------------------------------------
__global__ __launch_bounds__(128, 1)
void attn_kernel(float* __restrict__ out)
{
    const int b  = blockIdx.z;
    const int h  = blockIdx.y;
    const int qt = blockIdx.x;
    const int tid = threadIdx.x;
    const int qrow = qt * 128 + tid;
    const float scale = 0.125f;   // 1/sqrt(64)

    const size_t row3E = (size_t)3 * EMB;
    const float* basep = g_qkv + (size_t)b * SEQ * row3E;

    // Q row in packed pairs (pre-scaled)
    ull q2[HDIM / 2];
    {
        const float* qp = basep + (size_t)qrow * row3E + h * HDIM;
        #pragma unroll
        for (int d = 0; d < HDIM; d += 4) {
            float4 v = *reinterpret_cast<const float4*>(qp + d);
            q2[d / 2 + 0] = pk2(v.x * scale, v.y * scale);
            q2[d / 2 + 1] = pk2(v.z * scale, v.w * scale);
        }
    }

    float m = -INFINITY, l = 0.f;
    ull acc2[HDIM / 2];
    #pragma unroll
    for (int d = 0; d < HDIM / 2; ++d) acc2[d] = 0ull;

    __shared__ __align__(16) float Ks[32][HDIM];
    __shared__ __align__(16) float Vs[32][HDIM];

    const int kend = qt * 128 + 128;   // exclusive
    for (int k0 = 0; k0 < kend; k0 += 32) {
        __syncthreads();
        #pragma unroll
        for (int i = 0; i < 4; ++i) {
            int idx = tid + i * 128;       // float4 index 0..511
            int r = idx >> 4;
            int c = (idx & 15) << 2;
            const float* rowp = basep + (size_t)(k0 + r) * row3E + h * HDIM + c;
            *reinterpret_cast<float4*>(&Ks[r][c]) =
                *reinterpret_cast<const float4*>(rowp + EMB);
            *reinterpret_cast<float4*>(&Vs[r][c]) =
                *reinterpret_cast<const float4*>(rowp + 2 * EMB);
        }
        __syncthreads();

        // Scores for 32 keys with packed FMAs (4 keys at a time)
        float s[32];
        #pragma unroll
        for (int j = 0; j < 32; j += 4) {
            ull s0 = 0ull, s1 = 0ull, s2 = 0ull, s3 = 0ull;
            const ull* K0 = reinterpret_cast<const ull*>(&Ks[j + 0][0]);
            const ull* K1 = reinterpret_cast<const ull*>(&Ks[j + 1][0]);
            const ull* K2 = reinterpret_cast<const ull*>(&Ks[j + 2][0]);
            const ull* K3 = reinterpret_cast<const ull*>(&Ks[j + 3][0]);
            #pragma unroll
            for (int d2 = 0; d2 < HDIM / 2; ++d2) {
                ull qv = q2[d2];
                s0 = fma2(qv, K0[d2], s0);
                s1 = fma2(qv, K1[d2], s1);
                s2 = fma2(qv, K2[d2], s2);
                s3 = fma2(qv, K3[d2], s3);
            }
            float a0, b0, a1, b1, a2, b2, a3, b3;
            upk2(s0, a0, b0); upk2(s1, a1, b1);
            upk2(s2, a2, b2); upk2(s3, a3, b3);
            s[j + 0] = a0 + b0; s[j + 1] = a1 + b1;
            s[j + 2] = a2 + b2; s[j + 3] = a3 + b3;
        }

        // Causal mask (diagonal tiles only)
        if (k0 + 32 > qrow + 1) {
            #pragma unroll
            for (int j = 0; j < 32; ++j)
                if (k0 + j > qrow) s[j] = -INFINITY;
        }

        // Online softmax update
        float mt = m;
        #pragma unroll
        for (int j = 0; j < 32; ++j) mt = fmaxf(mt, s[j]);
        float corr = __expf(m - mt);
        m = mt;
        l *= corr;
        ull cc = pk2(corr, corr);
        #pragma unroll
        for (int d2 = 0; d2 < HDIM / 2; ++d2) acc2[d2] = mul2(acc2[d2], cc);

        #pragma unroll
        for (int j = 0; j < 32; ++j) {
            float p = __expf(s[j] - m);
            l += p;
            ull pp = pk2(p, p);
            const ull* V0 = reinterpret_cast<const ull*>(&Vs[j][0]);
            #pragma unroll
            for (int d2 = 0; d2 < HDIM / 2; ++d2)
                acc2[d2] = fma2(pp, V0[d2], acc2[d2]);
        }
    }

    const float inv = 1.f / l;
    float* op = out + ((size_t)b * SEQ + qrow) * EMB + h * HDIM;
    #pragma unroll
    for (int d2 = 0; d2 < HDIM / 2; d2 += 2) {
        float x0, x1, x2, x3;
        upk2(acc2[d2],     x0, x1);
        upk2(acc2[d2 + 1], x2, x3);
        float4 o = make_float4(x0 * inv, x1 * inv, x2 * inv, x3 * inv);
        *reinterpret_cast<float4*>(op + d2 * 2) = o;
    }
}

// ---------------------------------------------------------------------------
// Launch
// ---------------------------------------------------------------------------
extern "C" void kernel_launch(void* const* d_in, const int* in_sizes, int n_in,
                              void* d_out, int out_size)
{
    (void)in_sizes; (void)n_in; (void)out_size;
    const float* x     = (const float*)d_in[0];
    const float* W_qkv = (const float*)d_in[1];
    const float* b_qkv = (const float*)d_in[2];
    const float* W_o   = (const float*)d_in[3];
    const float* b_o   = (const float*)d_in[4];
    float* out = (float*)d_out;

    float* qkv_ptr  = nullptr;
    float* attn_ptr = nullptr;
    cudaGetSymbolAddress((void**)&qkv_ptr,  g_qkv);
    cudaGetSymbolAddress((void**)&attn_ptr, g_attn);

    // 1) QKV projection: [8192,1024] @ [1024,3072] + b
    {
        dim3 grid(3 * EMB / GBN, M_ROWS / GBM);
        gemm_tf32<<<grid, 256>>>(x, W_qkv, b_qkv, qkv_ptr, M_ROWS, 3 * EMB, EMB);
    }

    // 2) Causal multi-head attention
    {
        dim3 grid(SEQ / 128, HEADS, BATCH);
        attn_kernel<<<grid, 128>>>(attn_ptr);
    }

    // 3) Output projection: [8192,1024] @ [1024,1024] + b
    {
        dim3 grid(EMB / GBN, M_ROWS / GBM);
        gemm_tf32<<<grid, 256>>>(attn_ptr, W_o, b_o, out, M_ROWS, EMB, EMB);
    }
}

// round 3
// speedup vs baseline: 3.7871x; 2.0449x over previous
#include <cuda_runtime.h>
#include <cuda_bf16.h>
#include <math.h>

// Problem constants
#define BATCH 4
#define SEQ   2048
#define EMB   1024
#define HEADS 16
#define HDIM  64
#define M_ROWS (BATCH*SEQ)   // 8192

// Scratch (device globals — allocation-free per harness rules)
__device__ float g_qkv[(size_t)M_ROWS * 3 * EMB];   // [B*S, 3E]
__device__ float g_attn[(size_t)M_ROWS * EMB];      // [B*S, E]

// ---------------------------------------------------------------------------
// Helpers
// ---------------------------------------------------------------------------
__device__ __forceinline__ unsigned f2tf32(float x) {
    unsigned r;
    asm("cvt.rna.tf32.f32 %0, %1;" : "=r"(r) : "f"(x));
    return r;
}
__device__ __forceinline__ float tf32f(float x) {
    return __uint_as_float(f2tf32(x));
}

#define MMA_TF32(d0,d1,d2,d3, a0,a1,a2,a3, b0,b1)                           \
    asm volatile(                                                           \
        "mma.sync.aligned.m16n8k8.row.col.f32.tf32.tf32.f32 "               \
        "{%0,%1,%2,%3}, {%4,%5,%6,%7}, {%8,%9}, {%0,%1,%2,%3};"             \
        : "+f"(d0), "+f"(d1), "+f"(d2), "+f"(d3)                            \
        : "r"(a0), "r"(a1), "r"(a2), "r"(a3), "r"(b0), "r"(b1))

// ---------------------------------------------------------------------------
// tf32 tensor-core GEMM with bias: C[M,N] = A[M,K] @ B[K,N] + bias[N]
// Tile 128x128x16, 256 threads (8 warps), warp tile 64x32, double-buffered.
// ---------------------------------------------------------------------------
#define GBM 128
#define GBN 128
#define GBK 16
#define AST 20
#define BST 136

__global__ __launch_bounds__(256)
void gemm_tf32(const float* __restrict__ A, const float* __restrict__ B,
               const float* __restrict__ bias, float* __restrict__ C,
               int M, int N, int K)
{
    __shared__ __align__(16) float As[2][GBM][AST];
    __shared__ __align__(16) float Bs[2][GBK][BST];

    const int tid  = threadIdx.x;
    const int wid  = tid >> 5;
    const int lane = tid & 31;
    const int g = lane >> 2;
    const int t = lane & 3;

    const int bx = blockIdx.x;
    const int by = blockIdx.y;
    const int wm = (wid >> 2) * 64;
    const int wn = (wid & 3) * 32;

    const float* Ab = A + (size_t)by * GBM * K;
    const float* Bb = B + (size_t)bx * GBN;

    const int a_r0 = (tid + 0)   >> 2, a_c0 = ((tid + 0)   & 3) << 2;
    const int a_r1 = (tid + 256) >> 2, a_c1 = ((tid + 256) & 3) << 2;
    const int b_r0 = (tid + 0)   >> 5, b_c0 = ((tid + 0)   & 31) << 2;
    const int b_r1 = (tid + 256) >> 5, b_c1 = ((tid + 256) & 31) << 2;

    float acc[4][4][4];
    #pragma unroll
    for (int i = 0; i < 4; ++i)
        #pragma unroll
        for (int j = 0; j < 4; ++j)
            #pragma unroll
            for (int c = 0; c < 4; ++c) acc[i][j][c] = 0.f;

    float4 ra0, ra1, rb0, rb1;

    ra0 = *reinterpret_cast<const float4*>(Ab + (size_t)a_r0 * K + a_c0);
    ra1 = *reinterpret_cast<const float4*>(Ab + (size_t)a_r1 * K + a_c1);
    rb0 = *reinterpret_cast<const float4*>(Bb + (size_t)b_r0 * N + b_c0);
    rb1 = *reinterpret_cast<const float4*>(Bb + (size_t)b_r1 * N + b_c1);

    {
        float* ap0 = &As[0][a_r0][a_c0];
        ap0[0] = tf32f(ra0.x); ap0[1] = tf32f(ra0.y); ap0[2] = tf32f(ra0.z); ap0[3] = tf32f(ra0.w);
        float* ap1 = &As[0][a_r1][a_c1];
        ap1[0] = tf32f(ra1.x); ap1[1] = tf32f(ra1.y); ap1[2] = tf32f(ra1.z); ap1[3] = tf32f(ra1.w);
        float* bp0 = &Bs[0][b_r0][b_c0];
        bp0[0] = tf32f(rb0.x); bp0[1] = tf32f(rb0.y); bp0[2] = tf32f(rb0.z); bp0[3] = tf32f(rb0.w);
        float* bp1 = &Bs[0][b_r1][b_c1];
        bp1[0] = tf32f(rb1.x); bp1[1] = tf32f(rb1.y); bp1[2] = tf32f(rb1.z); bp1[3] = tf32f(rb1.w);
    }
    __syncthreads();

    const int ntiles = K / GBK;
    for (int kt = 0; kt < ntiles; ++kt) {
        const int st = kt & 1;

        if (kt + 1 < ntiles) {
            const int k0 = (kt + 1) * GBK;
            ra0 = *reinterpret_cast<const float4*>(Ab + (size_t)a_r0 * K + k0 + a_c0);
            ra1 = *reinterpret_cast<const float4*>(Ab + (size_t)a_r1 * K + k0 + a_c1);
            rb0 = *reinterpret_cast<const float4*>(Bb + (size_t)(k0 + b_r0) * N + b_c0);
            rb1 = *reinterpret_cast<const float4*>(Bb + (size_t)(k0 + b_r1) * N + b_c1);
        }

        #pragma unroll
        for (int ks = 0; ks < GBK; ks += 8) {
            unsigned a[4][4], b[4][2];
            #pragma unroll
            for (int mf = 0; mf < 4; ++mf) {
                const int mr = wm + mf * 16;
                a[mf][0] = __float_as_uint(As[st][mr + g    ][ks + t    ]);
                a[mf][1] = __float_as_uint(As[st][mr + g + 8][ks + t    ]);
                a[mf][2] = __float_as_uint(As[st][mr + g    ][ks + t + 4]);
                a[mf][3] = __float_as_uint(As[st][mr + g + 8][ks + t + 4]);
            }
            #pragma unroll
            for (int nf = 0; nf < 4; ++nf) {
                const int nc = wn + nf * 8 + g;
                b[nf][0] = __float_as_uint(Bs[st][ks + t    ][nc]);
                b[nf][1] = __float_as_uint(Bs[st][ks + t + 4][nc]);
            }
            #pragma unroll
            for (int mf = 0; mf < 4; ++mf)
                #pragma unroll
                for (int nf = 0; nf < 4; ++nf)
                    MMA_TF32(acc[mf][nf][0], acc[mf][nf][1], acc[mf][nf][2], acc[mf][nf][3],
                             a[mf][0], a[mf][1], a[mf][2], a[mf][3],
                             b[nf][0], b[nf][1]);
        }

        if (kt + 1 < ntiles) {
            const int ns = st ^ 1;
            float* ap0 = &As[ns][a_r0][a_c0];
            ap0[0] = tf32f(ra0.x); ap0[1] = tf32f(ra0.y); ap0[2] = tf32f(ra0.z); ap0[3] = tf32f(ra0.w);
            float* ap1 = &As[ns][a_r1][a_c1];
            ap1[0] = tf32f(ra1.x); ap1[1] = tf32f(ra1.y); ap1[2] = tf32f(ra1.z); ap1[3] = tf32f(ra1.w);
            float* bp0 = &Bs[ns][b_r0][b_c0];
            bp0[0] = tf32f(rb0.x); bp0[1] = tf32f(rb0.y); bp0[2] = tf32f(rb0.z); bp0[3] = tf32f(rb0.w);
            float* bp1 = &Bs[ns][b_r1][b_c1];
            bp1[0] = tf32f(rb1.x); bp1[1] = tf32f(rb1.y); bp1[2] = tf32f(rb1.z); bp1[3] = tf32f(rb1.w);
            __syncthreads();
        }
    }

    #pragma unroll
    for (int mf = 0; mf < 4; ++mf) {
        const int row = by * GBM + wm + mf * 16 + g;
        #pragma unroll
        for (int nf = 0; nf < 4; ++nf) {
            const int col = bx * GBN + wn + nf * 8 + 2 * t;
            float2 b2 = *reinterpret_cast<const float2*>(bias + col);
            float2 o0 = make_float2(acc[mf][nf][0] + b2.x, acc[mf][nf][1] + b2.y);
            float2 o1 = make_float2(acc[mf][nf][2] + b2.x, acc[mf][nf][3] + b2.y);
            *reinterpret_cast<float2*>(C + (size_t)row * N + col)       = o0;
            *reinterpret_cast<float2*>(C + (size_t)(row + 8) * N + col) = o1;
        }
    }
}

// ---------------------------------------------------------------------------
// Tensor-core causal flash attention (tf32 mma, fp32 softmax state).
// CTA: 128 threads / 4 warps. Q tile = 64 rows (16/warp), K/V tile = 64 keys.
// Q lives in registers as tf32 A-fragments for the whole CTA.
// P reuses the K SMEM buffer (scores are done with K when P is written).
// ---------------------------------------------------------------------------
#define KST 68   // K/P smem stride:  68 % 32 == 4  -> conflict-free frags
#define VST 72   // V smem stride:    72 % 32 == 8  -> conflict-free frags

__global__ __launch_bounds__(128)
void attn_tc(float* __restrict__ out)
{
    __shared__ __align__(16) float KP[64][KST];  // K tile, later P tile
    __shared__ __align__(16) float Vs[64][VST];

    const int b  = blockIdx.z;
    const int h  = blockIdx.y;
    const int qt = blockIdx.x;
    const int tid  = threadIdx.x;
    const int w    = tid >> 5;
    const int lane = tid & 31;
    const int g = lane >> 2;
    const int t = lane & 3;
    const int q0 = qt * 64;

    const size_t row3E = (size_t)3 * EMB;
    const float* basep = g_qkv + (size_t)b * SEQ * row3E;

    // Q fragments, pre-scaled by 1/sqrt(64), tf32 bits. rows w*16+g / +8.
    unsigned qa[8][4];
    {
        const float* q0p = basep + (size_t)(q0 + w * 16 + g) * row3E + h * HDIM;
        const float* q8p = q0p + 8 * row3E;
        #pragma unroll
        for (int ks = 0; ks < 8; ++ks) {
            qa[ks][0] = f2tf32(q0p[ks * 8 + t]     * 0.125f);
            qa[ks][1] = f2tf32(q8p[ks * 8 + t]     * 0.125f);
            qa[ks][2] = f2tf32(q0p[ks * 8 + t + 4] * 0.125f);
            qa[ks][3] = f2tf32(q8p[ks * 8 + t + 4] * 0.125f);
        }
    }

    float m0 = -INFINITY, m1 = -INFINITY, l0 = 0.f, l1 = 0.f;
    float o[8][4];
    #pragma unroll
    for (int nf = 0; nf < 8; ++nf)
        #pragma unroll
        for (int c = 0; c < 4; ++c) o[nf][c] = 0.f;

    for (int k0 = 0; k0 <= q0; k0 += 64) {
        __syncthreads();   // previous tile fully consumed

        // Load K,V tile (64x64 each), convert to tf32, swizzle-free pad strides
        #pragma unroll
        for (int i = 0; i < 8; ++i) {
            int idx = tid + i * 128;
            int r = idx >> 4;
            int c = (idx & 15) << 2;
            const float* rowp = basep + (size_t)(k0 + r) * row3E + h * HDIM + c;
            float4 kv = *reinterpret_cast<const float4*>(rowp + EMB);
            float4 vv = *reinterpret_cast<const float4*>(rowp + 2 * EMB);
            float4 kc = make_float4(tf32f(kv.x), tf32f(kv.y), tf32f(kv.z), tf32f(kv.w));
            float4 vc = make_float4(tf32f(vv.x), tf32f(vv.y), tf32f(vv.z), tf32f(vv.w));
            *reinterpret_cast<float4*>(&KP[r][c]) = kc;
            *reinterpret_cast<float4*>(&Vs[r][c]) = vc;
        }
        __syncthreads();

        // Scores: S[16x64] = Q @ K^T  (per warp)
        float s[8][4];
        #pragma unroll
        for (int nf = 0; nf < 8; ++nf)
            #pragma unroll
            for (int c = 0; c < 4; ++c) s[nf][c] = 0.f;

        #pragma unroll
        for (int ks = 0; ks < 8; ++ks) {
            unsigned bf[8][2];
            #pragma unroll
            for (int nf = 0; nf < 8; ++nf) {
                bf[nf][0] = __float_as_uint(KP[nf * 8 + g][ks * 8 + t]);
                bf[nf][1] = __float_as_uint(KP[nf * 8 + g][ks * 8 + t + 4]);
            }
            #pragma unroll
            for (int nf = 0; nf < 8; ++nf)
                MMA_TF32(s[nf][0], s[nf][1], s[nf][2], s[nf][3],
                         qa[ks][0], qa[ks][1], qa[ks][2], qa[ks][3],
                         bf[nf][0], bf[nf][1]);
        }

        // Causal mask (diagonal tile only). Row0 local = w*16+g, row1 = +8.
        if (k0 == q0) {
            const int r0l = w * 16 + g;
            #pragma unroll
            for (int nf = 0; nf < 8; ++nf) {
                const int c0 = nf * 8 + 2 * t;
                if (c0     > r0l)     s[nf][0] = -INFINITY;
                if (c0 + 1 > r0l)     s[nf][1] = -INFINITY;
                if (c0     > r0l + 8) s[nf][2] = -INFINITY;
                if (c0 + 1 > r0l + 8) s[nf][3] = -INFINITY;
            }
        }

        // Online softmax: rows g (c0,c1) and g+8 (c2,c3)
        float tm0 = -INFINITY, tm1 = -INFINITY;
        #pragma unroll
        for (int nf = 0; nf < 8; ++nf) {
            tm0 = fmaxf(tm0, fmaxf(s[nf][0], s[nf][1]));
            tm1 = fmaxf(tm1, fmaxf(s[nf][2], s[nf][3]));
        }
        tm0 = fmaxf(tm0, __shfl_xor_sync(0xffffffffu, tm0, 1));
        tm0 = fmaxf(tm0, __shfl_xor_sync(0xffffffffu, tm0, 2));
        tm1 = fmaxf(tm1, __shfl_xor_sync(0xffffffffu, tm1, 1));
        tm1 = fmaxf(tm1, __shfl_xor_sync(0xffffffffu, tm1, 2));

        const float m0n = fmaxf(m0, tm0);
        const float m1n = fmaxf(m1, tm1);
        const float c0 = __expf(m0 - m0n);
        const float c1 = __expf(m1 - m1n);
        m0 = m0n; m1 = m1n;

        float ls0 = 0.f, ls1 = 0.f;
        #pragma unroll
        for (int nf = 0; nf < 8; ++nf) {
            s[nf][0] = __expf(s[nf][0] - m0n); ls0 += s[nf][0];
            s[nf][1] = __expf(s[nf][1] - m0n); ls0 += s[nf][1];
            s[nf][2] = __expf(s[nf][2] - m1n); ls1 += s[nf][2];
            s[nf][3] = __expf(s[nf][3] - m1n); ls1 += s[nf][3];
        }
        ls0 += __shfl_xor_sync(0xffffffffu, ls0, 1);
        ls0 += __shfl_xor_sync(0xffffffffu, ls0, 2);
        ls1 += __shfl_xor_sync(0xffffffffu, ls1, 1);
        ls1 += __shfl_xor_sync(0xffffffffu, ls1, 2);
        l0 = l0 * c0 + ls0;
        l1 = l1 * c1 + ls1;

        #pragma unroll
        for (int nf = 0; nf < 8; ++nf) {
            o[nf][0] *= c0; o[nf][1] *= c0;
            o[nf][2] *= c1; o[nf][3] *= c1;
        }

        // All warps finished reading K before P overwrites the buffer
        __syncthreads();

        const int pr0 = w * 16 + g;
        #pragma unroll
        for (int nf = 0; nf < 8; ++nf) {
            const int pc = nf * 8 + 2 * t;
            KP[pr0][pc]         = tf32f(s[nf][0]);
            KP[pr0][pc + 1]     = tf32f(s[nf][1]);
            KP[pr0 + 8][pc]     = tf32f(s[nf][2]);
            KP[pr0 + 8][pc + 1] = tf32f(s[nf][3]);
        }
        __syncwarp();

        // O += P @ V   (A from P smem, B from V smem)
        #pragma unroll
        for (int ks = 0; ks < 8; ++ks) {
            unsigned pa[4];
            pa[0] = __float_as_uint(KP[pr0    ][ks * 8 + t]);
            pa[1] = __float_as_uint(KP[pr0 + 8][ks * 8 + t]);
            pa[2] = __float_as_uint(KP[pr0    ][ks * 8 + t + 4]);
            pa[3] = __float_as_uint(KP[pr0 + 8][ks * 8 + t + 4]);
            #pragma unroll
            for (int nf = 0; nf < 8; ++nf) {
                unsigned b0 = __float_as_uint(Vs[ks * 8 + t    ][nf * 8 + g]);
                unsigned b1 = __float_as_uint(Vs[ks * 8 + t + 4][nf * 8 + g]);
                MMA_TF32(o[nf][0], o[nf][1], o[nf][2], o[nf][3],
                         pa[0], pa[1], pa[2], pa[3], b0, b1);
            }
        }
    }

    // Epilogue
    const float inv0 = 1.f / l0;
    const float inv1 = 1.f / l1;
    const int gr0 = q0 + w * 16 + g;
    float* op0 = out + ((size_t)b * SEQ + gr0) * EMB + h * HDIM;
    float* op1 = op0 + 8 * EMB;
    #pragma unroll
    for (int nf = 0; nf < 8; ++nf) {
        const int col = nf * 8 + 2 * t;
        *reinterpret_cast<float2*>(op0 + col) =
            make_float2(o[nf][0] * inv0, o[nf][1] * inv0);
        *reinterpret_cast<float2*>(op1 + col) =
            make_float2(o[nf][2] * inv1, o[nf][3] * inv1);
    }
}

// ---------------------------------------------------------------------------
// Launch
// ---------------------------------------------------------------------------
extern "C" void kernel_launch(void* const* d_in, const int* in_sizes, int n_in,
                              void* d_out, int out_size)
{
    (void)in_sizes; (void)n_in; (void)out_size;
    const float* x     = (const float*)d_in[0];
    const float* W_qkv = (const float*)d_in[1];
    const float* b_qkv = (const float*)d_in[2];
    const float* W_o   = (const float*)d_in[3];
    const float* b_o   = (const float*)d_in[4];
    float* out = (float*)d_out;

    float* qkv_ptr  = nullptr;
    float* attn_ptr = nullptr;
    cudaGetSymbolAddress((void**)&qkv_ptr,  g_qkv);
    cudaGetSymbolAddress((void**)&attn_ptr, g_attn);

    // 1) QKV projection
    {
        dim3 grid(3 * EMB / GBN, M_ROWS / GBM);
        gemm_tf32<<<grid, 256>>>(x, W_qkv, b_qkv, qkv_ptr, M_ROWS, 3 * EMB, EMB);
    }
    // 2) Tensor-core causal flash attention
    {
        dim3 grid(SEQ / 64, HEADS, BATCH);
        attn_tc<<<grid, 128>>>(attn_ptr);
    }
    // 3) Output projection
    {
        dim3 grid(EMB / GBN, M_ROWS / GBM);
        gemm_tf32<<<grid, 256>>>(attn_ptr, W_o, b_o, out, M_ROWS, EMB, EMB);
    }
}

// round 6
// speedup vs baseline: 4.2806x; 1.1303x over previous
#include <cuda_runtime.h>
#include <cuda_fp16.h>
#include <math.h>
#include <stdint.h>
#include <stddef.h>

// Problem constants
#define BATCH 4
#define SEQ   2048
#define EMB   1024
#define HEADS 16
#define HDIM  64
#define M_ROWS (BATCH*SEQ)   // 8192

// Scratch (device globals — allocation-free per harness rules)
__device__ float g_qkv[(size_t)M_ROWS * 3 * EMB];   // [B*S, 3E]
__device__ float g_attn[(size_t)M_ROWS * EMB];      // [B*S, E]

// ---------------------------------------------------------------------------
// Helpers
// ---------------------------------------------------------------------------
__device__ __forceinline__ unsigned f2tf32(float x) {
    unsigned r;
    asm("cvt.rna.tf32.f32 %0, %1;" : "=r"(r) : "f"(x));
    return r;
}
__device__ __forceinline__ float tf32f(float x) {
    return __uint_as_float(f2tf32(x));
}
__device__ __forceinline__ uint32_t ph2(float a, float b) {
    __half2 h = __floats2half2_rn(a, b);
    return *reinterpret_cast<uint32_t*>(&h);
}
__device__ __forceinline__ uint32_t s2u(const void* p) {
    uint32_t r;
    asm("{ .reg .u64 t; cvta.to.shared.u64 t, %1; cvt.u32.u64 %0, t; }"
        : "=r"(r) : "l"(p));
    return r;
}

#define MMA_TF32(d0,d1,d2,d3, a0,a1,a2,a3, b0,b1)                           \
    asm volatile(                                                           \
        "mma.sync.aligned.m16n8k8.row.col.f32.tf32.tf32.f32 "               \
        "{%0,%1,%2,%3}, {%4,%5,%6,%7}, {%8,%9}, {%0,%1,%2,%3};"             \
        : "+f"(d0), "+f"(d1), "+f"(d2), "+f"(d3)                            \
        : "r"(a0), "r"(a1), "r"(a2), "r"(a3), "r"(b0), "r"(b1))

#define MMA_F16(d0,d1,d2,d3, a0,a1,a2,a3, b0,b1)                            \
    asm volatile(                                                           \
        "mma.sync.aligned.m16n8k16.row.col.f32.f16.f16.f32 "                \
        "{%0,%1,%2,%3}, {%4,%5,%6,%7}, {%8,%9}, {%0,%1,%2,%3};"             \
        : "+f"(d0), "+f"(d1), "+f"(d2), "+f"(d3)                            \
        : "r"(a0), "r"(a1), "r"(a2), "r"(a3), "r"(b0), "r"(b1))

__device__ __forceinline__ void ldsm_x2(uint32_t& r0, uint32_t& r1, uint32_t addr) {
    asm volatile("ldmatrix.sync.aligned.m8n8.x2.shared.b16 {%0,%1}, [%2];"
                 : "=r"(r0), "=r"(r1) : "r"(addr));
}
__device__ __forceinline__ void ldsm_x2t(uint32_t& r0, uint32_t& r1, uint32_t addr) {
    asm volatile("ldmatrix.sync.aligned.m8n8.x2.trans.shared.b16 {%0,%1}, [%2];"
                 : "=r"(r0), "=r"(r1) : "r"(addr));
}

// ---------------------------------------------------------------------------
// tf32 GEMM, CTA tile 128x256x16, 8 warps, warp tile 64x64, double-buffered.
// A smem rows k-interleaved (k, k+4 adjacent) for LDS.64 fragment loads.
// B smem [k][n] with pad-264 (conflict-free 8t+g bank map).
// ---------------------------------------------------------------------------
#define GBM 128
#define GBN 256
#define GBK 16
#define AST 20
#define BST 264
#define A_STG (GBM * AST)          // floats per stage: 2560
#define B_STG (GBK * BST)          // floats per stage: 4224
#define GSMEM ((2 * A_STG + 2 * B_STG) * 4)   // 54272 bytes

__global__ __launch_bounds__(256)
void gemm_tf32(const float* __restrict__ A, const float* __restrict__ B,
               const float* __restrict__ bias, float* __restrict__ C,
               int M, int N, int K)
{
    extern __shared__ float sm[];
    float* As = sm;                  // [2][128][20]
    float* Bs = sm + 2 * A_STG;      // [2][16][264]

    const int tid  = threadIdx.x;
    const int wid  = tid >> 5;
    const int lane = tid & 31;
    const int g = lane >> 2;
    const int t = lane & 3;
    const int wm = (wid >> 2) * 64;      // 0 / 64
    const int wn = (wid & 3) * 64;       // 0/64/128/192
    const int n0 = blockIdx.x * GBN;
    const int m0 = blockIdx.y * GBM;

    const float* Ab = A + (size_t)m0 * K;
    const float* Bb = B + n0;

    // A: 2 float4 per thread
    const int a_r0 = tid >> 2,         a_c0 = (tid & 3) << 2;
    const int a_r1 = (tid + 256) >> 2, a_c1 = ((tid + 256) & 3) << 2;
    const int a_p0 = ((a_c0 >> 2) & 1) + (a_c0 & 8);
    const int a_p1 = ((a_c1 >> 2) & 1) + (a_c1 & 8);

    float acc[4][8][4];
    #pragma unroll
    for (int i = 0; i < 4; ++i)
        #pragma unroll
        for (int j = 0; j < 8; ++j)
            #pragma unroll
            for (int c = 0; c < 4; ++c) acc[i][j][c] = 0.f;

    float4 ra0, ra1, rb[4];

    // prologue: load chunk 0
    ra0 = *reinterpret_cast<const float4*>(Ab + (size_t)a_r0 * K + a_c0);
    ra1 = *reinterpret_cast<const float4*>(Ab + (size_t)a_r1 * K + a_c1);
    #pragma unroll
    for (int i = 0; i < 4; ++i) {
        int idx = tid + i * 256;
        int r = idx >> 6, c = (idx & 63) << 2;
        rb[i] = *reinterpret_cast<const float4*>(Bb + (size_t)r * N + c);
    }

    // store stage 0
    {
        float* a0 = &As[a_r0 * AST + a_p0];
        a0[0] = tf32f(ra0.x); a0[2] = tf32f(ra0.y); a0[4] = tf32f(ra0.z); a0[6] = tf32f(ra0.w);
        float* a1 = &As[a_r1 * AST + a_p1];
        a1[0] = tf32f(ra1.x); a1[2] = tf32f(ra1.y); a1[4] = tf32f(ra1.z); a1[6] = tf32f(ra1.w);
        #pragma unroll
        for (int i = 0; i < 4; ++i) {
            int idx = tid + i * 256;
            int r = idx >> 6, c = (idx & 63) << 2;
            float4 o = make_float4(tf32f(rb[i].x), tf32f(rb[i].y),
                                   tf32f(rb[i].z), tf32f(rb[i].w));
            *reinterpret_cast<float4*>(&Bs[r * BST + c]) = o;
        }
    }
    __syncthreads();

    const int ntiles = K / GBK;
    for (int kt = 0; kt < ntiles; ++kt) {
        const int st = kt & 1;
        const float* Asb = As + st * A_STG;
        const float* Bsb = Bs + st * B_STG;

        if (kt + 1 < ntiles) {
            const int k0 = (kt + 1) * GBK;
            ra0 = *reinterpret_cast<const float4*>(Ab + (size_t)a_r0 * K + k0 + a_c0);
            ra1 = *reinterpret_cast<const float4*>(Ab + (size_t)a_r1 * K + k0 + a_c1);
            #pragma unroll
            for (int i = 0; i < 4; ++i) {
                int idx = tid + i * 256;
                int r = idx >> 6, c = (idx & 63) << 2;
                rb[i] = *reinterpret_cast<const float4*>(Bb + (size_t)(k0 + r) * N + c);
            }
        }

        #pragma unroll
        for (int ks = 0; ks < 2; ++ks) {
            const int kb = ks * 8 + 2 * t;
            float2 af0[4], af1[4];
            #pragma unroll
            for (int mf = 0; mf < 4; ++mf) {
                int r = wm + mf * 16 + g;
                af0[mf] = *reinterpret_cast<const float2*>(&Asb[r * AST + kb]);
                af1[mf] = *reinterpret_cast<const float2*>(&Asb[(r + 8) * AST + kb]);
            }
            float2 bf[8];
            #pragma unroll
            for (int nf = 0; nf < 8; ++nf) {
                int n = wn + nf * 8 + g;
                bf[nf].x = Bsb[(ks * 8 + t) * BST + n];
                bf[nf].y = Bsb[(ks * 8 + t + 4) * BST + n];
            }
            #pragma unroll
            for (int mf = 0; mf < 4; ++mf) {
                unsigned a0 = __float_as_uint(af0[mf].x);
                unsigned a1 = __float_as_uint(af1[mf].x);
                unsigned a2 = __float_as_uint(af0[mf].y);
                unsigned a3 = __float_as_uint(af1[mf].y);
                #pragma unroll
                for (int nf = 0; nf < 8; ++nf)
                    MMA_TF32(acc[mf][nf][0], acc[mf][nf][1],
                             acc[mf][nf][2], acc[mf][nf][3],
                             a0, a1, a2, a3,
                             __float_as_uint(bf[nf].x), __float_as_uint(bf[nf].y));
            }
        }

        if (kt + 1 < ntiles) {
            float* Asn = As + (st ^ 1) * A_STG;
            float* Bsn = Bs + (st ^ 1) * B_STG;
            float* a0 = &Asn[a_r0 * AST + a_p0];
            a0[0] = tf32f(ra0.x); a0[2] = tf32f(ra0.y); a0[4] = tf32f(ra0.z); a0[6] = tf32f(ra0.w);
            float* a1 = &Asn[a_r1 * AST + a_p1];
            a1[0] = tf32f(ra1.x); a1[2] = tf32f(ra1.y); a1[4] = tf32f(ra1.z); a1[6] = tf32f(ra1.w);
            #pragma unroll
            for (int i = 0; i < 4; ++i) {
                int idx = tid + i * 256;
                int r = idx >> 6, c = (idx & 63) << 2;
                float4 o = make_float4(tf32f(rb[i].x), tf32f(rb[i].y),
                                       tf32f(rb[i].z), tf32f(rb[i].w));
                *reinterpret_cast<float4*>(&Bsn[r * BST + c]) = o;
            }
            __syncthreads();
        }
    }

    // epilogue
    #pragma unroll
    for (int mf = 0; mf < 4; ++mf) {
        const int row = m0 + wm + mf * 16 + g;
        #pragma unroll
        for (int nf = 0; nf < 8; ++nf) {
            const int col = n0 + wn + nf * 8 + 2 * t;
            float2 b2 = *reinterpret_cast<const float2*>(bias + col);
            float2 o0 = make_float2(acc[mf][nf][0] + b2.x, acc[mf][nf][1] + b2.y);
            float2 o1 = make_float2(acc[mf][nf][2] + b2.x, acc[mf][nf][3] + b2.y);
            *reinterpret_cast<float2*>(C + (size_t)row * N + col)       = o0;
            *reinterpret_cast<float2*>(C + (size_t)(row + 8) * N + col) = o1;
        }
    }
}

// ---------------------------------------------------------------------------
// f16 tensor-core causal flash attention (m16n8k16, ldmatrix, register P).
// CTA: 128 threads / 4 warps; 64-query tile (16/warp); 64-key K/V smem tiles.
// fp32 softmax state and accumulators; K/V/P/Q in f16.
// ---------------------------------------------------------------------------
#define KSTH 72    // halves per smem row (64 + 8 pad); 144B stride

__global__ __launch_bounds__(128)
void attn_f16(float* __restrict__ out)
{
    __shared__ __align__(16) __half Ks[64][KSTH];
    __shared__ __align__(16) __half Vs[64][KSTH];

    const int b  = blockIdx.z;
    const int h  = blockIdx.y;
    const int qt = blockIdx.x;
    const int tid  = threadIdx.x;
    const int w    = tid >> 5;
    const int lane = tid & 31;
    const int g = lane >> 2;
    const int t = lane & 3;
    const int q0 = qt * 64;

    const size_t row3E = (size_t)3 * EMB;
    const float* basep = g_qkv + (size_t)b * SEQ * row3E;

    // Q fragments (f16x2, pre-scaled by 1/8): 4 ksteps of 16
    uint32_t qa[4][4];
    {
        const float* q0p = basep + (size_t)(q0 + w * 16 + g) * row3E + h * HDIM;
        const float* q8p = q0p + 8 * row3E;
        #pragma unroll
        for (int ks = 0; ks < 4; ++ks) {
            float2 v0 = *reinterpret_cast<const float2*>(q0p + ks * 16 + 2 * t);
            float2 v1 = *reinterpret_cast<const float2*>(q8p + ks * 16 + 2 * t);
            float2 v2 = *reinterpret_cast<const float2*>(q0p + ks * 16 + 8 + 2 * t);
            float2 v3 = *reinterpret_cast<const float2*>(q8p + ks * 16 + 8 + 2 * t);
            qa[ks][0] = ph2(v0.x * 0.125f, v0.y * 0.125f);
            qa[ks][1] = ph2(v1.x * 0.125f, v1.y * 0.125f);
            qa[ks][2] = ph2(v2.x * 0.125f, v2.y * 0.125f);
            qa[ks][3] = ph2(v3.x * 0.125f, v3.y * 0.125f);
        }
    }

    float m0 = -INFINITY, m1 = -INFINITY, l0 = 0.f, l1 = 0.f;
    float o[8][4];
    #pragma unroll
    for (int nf = 0; nf < 8; ++nf)
        #pragma unroll
        for (int c = 0; c < 4; ++c) o[nf][c] = 0.f;

    const uint32_t ksu = s2u(Ks);
    const uint32_t vsu = s2u(Vs);
    const int krow = lane & 7;          // ldmatrix row within block
    const int khalf = (lane >> 3) & 1;  // block select for K
    const int vrow = lane & 15;         // V rows across both blocks

    for (int k0 = 0; k0 <= q0; k0 += 64) {
        __syncthreads();
        // load K/V tile (fp32 -> f16)
        #pragma unroll
        for (int i = 0; i < 8; ++i) {
            int idx = tid + i * 128;
            int r = idx >> 4;
            int c = (idx & 15) << 2;
            const float* rowp = basep + (size_t)(k0 + r) * row3E + h * HDIM + c;
            float4 kv = *reinterpret_cast<const float4*>(rowp + EMB);
            float4 vv = *reinterpret_cast<const float4*>(rowp + 2 * EMB);
            uint2 kp = make_uint2(ph2(kv.x, kv.y), ph2(kv.z, kv.w));
            uint2 vp = make_uint2(ph2(vv.x, vv.y), ph2(vv.z, vv.w));
            *reinterpret_cast<uint2*>(&Ks[r][c]) = kp;
            *reinterpret_cast<uint2*>(&Vs[r][c]) = vp;
        }
        __syncthreads();

        // scores: S[16x64] = Q @ K^T
        float s[8][4];
        #pragma unroll
        for (int nf = 0; nf < 8; ++nf)
            #pragma unroll
            for (int c = 0; c < 4; ++c) s[nf][c] = 0.f;

        #pragma unroll
        for (int nf = 0; nf < 8; ++nf) {
            #pragma unroll
            for (int ks = 0; ks < 4; ++ks) {
                uint32_t b0, b1;
                uint32_t addr = ksu + (uint32_t)(nf * 8 + krow) * (KSTH * 2)
                              + (uint32_t)(ks * 16 + khalf * 8) * 2;
                ldsm_x2(b0, b1, addr);
                MMA_F16(s[nf][0], s[nf][1], s[nf][2], s[nf][3],
                        qa[ks][0], qa[ks][1], qa[ks][2], qa[ks][3], b0, b1);
            }
        }

        // causal mask (diagonal tile)
        if (k0 == q0) {
            const int r0l = w * 16 + g;
            #pragma unroll
            for (int nf = 0; nf < 8; ++nf) {
                const int c0 = nf * 8 + 2 * t;
                if (c0     > r0l)     s[nf][0] = -INFINITY;
                if (c0 + 1 > r0l)     s[nf][1] = -INFINITY;
                if (c0     > r0l + 8) s[nf][2] = -INFINITY;
                if (c0 + 1 > r0l + 8) s[nf][3] = -INFINITY;
            }
        }

        // online softmax (rows g / g+8)
        float tm0 = -INFINITY, tm1 = -INFINITY;
        #pragma unroll
        for (int nf = 0; nf < 8; ++nf) {
            tm0 = fmaxf(tm0, fmaxf(s[nf][0], s[nf][1]));
            tm1 = fmaxf(tm1, fmaxf(s[nf][2], s[nf][3]));
        }
        tm0 = fmaxf(tm0, __shfl_xor_sync(0xffffffffu, tm0, 1));
        tm0 = fmaxf(tm0, __shfl_xor_sync(0xffffffffu, tm0, 2));
        tm1 = fmaxf(tm1, __shfl_xor_sync(0xffffffffu, tm1, 1));
        tm1 = fmaxf(tm1, __shfl_xor_sync(0xffffffffu, tm1, 2));

        const float m0n = fmaxf(m0, tm0);
        const float m1n = fmaxf(m1, tm1);
        const float c0 = __expf(m0 - m0n);
        const float c1 = __expf(m1 - m1n);
        m0 = m0n; m1 = m1n;

        float ls0 = 0.f, ls1 = 0.f;
        #pragma unroll
        for (int nf = 0; nf < 8; ++nf) {
            s[nf][0] = __expf(s[nf][0] - m0n); ls0 += s[nf][0];
            s[nf][1] = __expf(s[nf][1] - m0n); ls0 += s[nf][1];
            s[nf][2] = __expf(s[nf][2] - m1n); ls1 += s[nf][2];
            s[nf][3] = __expf(s[nf][3] - m1n); ls1 += s[nf][3];
        }
        ls0 += __shfl_xor_sync(0xffffffffu, ls0, 1);
        ls0 += __shfl_xor_sync(0xffffffffu, ls0, 2);
        ls1 += __shfl_xor_sync(0xffffffffu, ls1, 1);
        ls1 += __shfl_xor_sync(0xffffffffu, ls1, 2);
        l0 = l0 * c0 + ls0;
        l1 = l1 * c1 + ls1;

        #pragma unroll
        for (int nf = 0; nf < 8; ++nf) {
            o[nf][0] *= c0; o[nf][1] *= c0;
            o[nf][2] *= c1; o[nf][3] *= c1;
        }

        // P -> f16 A-fragments, in registers (C-frag layout == A-frag layout)
        uint32_t pa[4][4];
        #pragma unroll
        for (int ks = 0; ks < 4; ++ks) {
            pa[ks][0] = ph2(s[2 * ks][0],     s[2 * ks][1]);
            pa[ks][1] = ph2(s[2 * ks][2],     s[2 * ks][3]);
            pa[ks][2] = ph2(s[2 * ks + 1][0], s[2 * ks + 1][1]);
            pa[ks][3] = ph2(s[2 * ks + 1][2], s[2 * ks + 1][3]);
        }

        // O += P @ V  (V via ldmatrix.trans)
        #pragma unroll
        for (int nf = 0; nf < 8; ++nf) {
            #pragma unroll
            for (int ks = 0; ks < 4; ++ks) {
                uint32_t v0, v1;
                uint32_t addr = vsu + (uint32_t)(ks * 16 + vrow) * (KSTH * 2)
                              + (uint32_t)nf * 16;
                ldsm_x2t(v0, v1, addr);
                MMA_F16(o[nf][0], o[nf][1], o[nf][2], o[nf][3],
                        pa[ks][0], pa[ks][1], pa[ks][2], pa[ks][3], v0, v1);
            }
        }
    }

    // epilogue (fp32 out)
    const float inv0 = 1.f / l0;
    const float inv1 = 1.f / l1;
    const int gr0 = q0 + w * 16 + g;
    float* op0 = out + ((size_t)b * SEQ + gr0) * EMB + h * HDIM;
    float* op1 = op0 + 8 * EMB;
    #pragma unroll
    for (int nf = 0; nf < 8; ++nf) {
        const int col = nf * 8 + 2 * t;
        *reinterpret_cast<float2*>(op0 + col) =
            make_float2(o[nf][0] * inv0, o[nf][1] * inv0);
        *reinterpret_cast<float2*>(op1 + col) =
            make_float2(o[nf][2] * inv1, o[nf][3] * inv1);
    }
}

// ---------------------------------------------------------------------------
// Launch
// ---------------------------------------------------------------------------
extern "C" void kernel_launch(void* const* d_in, const int* in_sizes, int n_in,
                              void* d_out, int out_size)
{
    (void)in_sizes; (void)n_in; (void)out_size;
    const float* x     = (const float*)d_in[0];
    const float* W_qkv = (const float*)d_in[1];
    const float* b_qkv = (const float*)d_in[2];
    const float* W_o   = (const float*)d_in[3];
    const float* b_o   = (const float*)d_in[4];
    float* out = (float*)d_out;

    float* qkv_ptr  = nullptr;
    float* attn_ptr = nullptr;
    cudaGetSymbolAddress((void**)&qkv_ptr,  g_qkv);
    cudaGetSymbolAddress((void**)&attn_ptr, g_attn);

    cudaFuncSetAttribute(gemm_tf32, cudaFuncAttributeMaxDynamicSharedMemorySize,
                         GSMEM);

    // 1) QKV projection: [8192,1024] @ [1024,3072] + b
    gemm_tf32<<<dim3(3 * EMB / GBN, M_ROWS / GBM), 256, GSMEM>>>(
        x, W_qkv, b_qkv, qkv_ptr, M_ROWS, 3 * EMB, EMB);

    // 2) f16 tensor-core causal flash attention
    attn_f16<<<dim3(SEQ / 64, HEADS, BATCH), 128>>>(attn_ptr);

    // 3) Output projection: [8192,1024] @ [1024,1024] + b
    gemm_tf32<<<dim3(EMB / GBN, M_ROWS / GBM), 256, GSMEM>>>(
        attn_ptr, W_o, b_o, out, M_ROWS, EMB, EMB);
}

// round 7
// speedup vs baseline: 8.0213x; 1.8739x over previous
#include <cuda_runtime.h>
#include <cuda_fp16.h>
#include <math.h>
#include <stdint.h>
#include <stddef.h>

// Problem constants
#define BATCH 4
#define SEQ   2048
#define EMB   1024
#define HEADS 16
#define HDIM  64
#define M_ROWS (BATCH*SEQ)   // 8192

// Scratch (device globals — allocation-free per harness rules)
__device__ __half g_xh[(size_t)M_ROWS * EMB];        // x f16
__device__ __half g_wqkvh[(size_t)EMB * 3 * EMB];    // W_qkv f16 [K,N]
__device__ __half g_woh[(size_t)EMB * EMB];          // W_o f16 [K,N]
__device__ __half g_qkvh[(size_t)M_ROWS * 3 * EMB];  // qkv f16
__device__ __half g_attnh[(size_t)M_ROWS * EMB];     // attention out f16

// ---------------------------------------------------------------------------
// Helpers
// ---------------------------------------------------------------------------
__device__ __forceinline__ uint32_t ph2(float a, float b) {
    __half2 h = __floats2half2_rn(a, b);
    return *reinterpret_cast<uint32_t*>(&h);
}
__device__ __forceinline__ uint32_t s2u(const void* p) {
    uint32_t r;
    asm("{ .reg .u64 t; cvta.to.shared.u64 t, %1; cvt.u32.u64 %0, t; }"
        : "=r"(r) : "l"(p));
    return r;
}

#define MMA_F16(d0,d1,d2,d3, a0,a1,a2,a3, b0,b1)                            \
    asm volatile(                                                           \
        "mma.sync.aligned.m16n8k16.row.col.f32.f16.f16.f32 "                \
        "{%0,%1,%2,%3}, {%4,%5,%6,%7}, {%8,%9}, {%0,%1,%2,%3};"             \
        : "+f"(d0), "+f"(d1), "+f"(d2), "+f"(d3)                            \
        : "r"(a0), "r"(a1), "r"(a2), "r"(a3), "r"(b0), "r"(b1))

__device__ __forceinline__ void ldsm_x4(uint32_t& r0, uint32_t& r1,
                                        uint32_t& r2, uint32_t& r3, uint32_t addr) {
    asm volatile("ldmatrix.sync.aligned.m8n8.x4.shared.b16 {%0,%1,%2,%3}, [%4];"
                 : "=r"(r0), "=r"(r1), "=r"(r2), "=r"(r3) : "r"(addr));
}
__device__ __forceinline__ void ldsm_x2(uint32_t& r0, uint32_t& r1, uint32_t addr) {
    asm volatile("ldmatrix.sync.aligned.m8n8.x2.shared.b16 {%0,%1}, [%2];"
                 : "=r"(r0), "=r"(r1) : "r"(addr));
}
__device__ __forceinline__ void ldsm_x2t(uint32_t& r0, uint32_t& r1, uint32_t addr) {
    asm volatile("ldmatrix.sync.aligned.m8n8.x2.trans.shared.b16 {%0,%1}, [%2];"
                 : "=r"(r0), "=r"(r1) : "r"(addr));
}
__device__ __forceinline__ void cp16(uint32_t dst, const void* src) {
    asm volatile("cp.async.cg.shared.global [%0], [%1], 16;"
                 :: "r"(dst), "l"(src) : "memory");
}

// ---------------------------------------------------------------------------
// Pre-pass: f32 -> f16 (vectorized)
// ---------------------------------------------------------------------------
__global__ __launch_bounds__(256)
void f32_to_f16(const float* __restrict__ in, __half* __restrict__ out, int n4) {
    int i = blockIdx.x * 256 + threadIdx.x;
    if (i < n4) {
        float4 v = reinterpret_cast<const float4*>(in)[i];
        uint2 o = make_uint2(ph2(v.x, v.y), ph2(v.z, v.w));
        reinterpret_cast<uint2*>(out)[i] = o;
    }
}

// ---------------------------------------------------------------------------
// f16 tensor-core GEMM: C[M,N] = A[M,K](f16) @ B[K,N](f16) + bias(f32)
// CTA 128x128x32, 256 threads / 8 warps, warp tile 64x32.
// A frags: ldmatrix.x4 on [m][k] tiles (pad 40 halves = 80B).
// B frags: ldmatrix.x2.trans on [k][n] tiles (pad 136 halves = 272B).
// cp.async double buffering; fp32 accum; OutT = __half or float.
// ---------------------------------------------------------------------------
#define GBM 128
#define GBN 128
#define GBK 32
#define APAD 40                    // halves per A row
#define BPAD 136                   // halves per B row
#define ASTG_B (GBM * APAD * 2)    // 10240 B
#define BSTG_B (GBK * BPAD * 2)    // 8704 B
#define GSMEM (2 * (ASTG_B + BSTG_B))   // 37888 B

template <typename OutT>
__global__ __launch_bounds__(256)
void gemm_f16(const __half* __restrict__ A, const __half* __restrict__ B,
              const float* __restrict__ bias, OutT* __restrict__ C,
              int M, int N, int K)
{
    extern __shared__ __align__(16) char smem[];
    const int tid  = threadIdx.x;
    const int wid  = tid >> 5;
    const int lane = tid & 31;
    const int g = lane >> 2;
    const int t = lane & 3;
    const int wm = (wid >> 2) * 64;   // 0 / 64
    const int wn = (wid & 3) * 32;    // 0/32/64/96
    const int n0 = blockIdx.x * GBN;
    const int m0 = blockIdx.y * GBM;

    const uint32_t smA_u = s2u(smem);
    const uint32_t smB_u = smA_u + 2 * ASTG_B;

    const __half* Ab = A + (size_t)m0 * K;
    const __half* Bb = B + n0;

    float acc[4][4][4];
    #pragma unroll
    for (int i = 0; i < 4; ++i)
        #pragma unroll
        for (int j = 0; j < 4; ++j)
            #pragma unroll
            for (int c = 0; c < 4; ++c) acc[i][j][c] = 0.f;

    // chunk loader: A 128x32 halves, B 32x128 halves, 16B cp.async each
    const int a_r0 = tid >> 2,         a_c0 = (tid & 3);          // 2 per thread
    const int a_r1 = (tid + 256) >> 2, a_c1 = ((tid + 256) & 3);
    const int b_r0 = tid >> 4,         b_c0 = (tid & 15);
    const int b_r1 = (tid + 256) >> 4, b_c1 = ((tid + 256) & 15);

    const int ntiles = K / GBK;

    {   // prologue: chunk 0 -> stage 0
        cp16(smA_u + a_r0 * (APAD * 2) + a_c0 * 16, Ab + (size_t)a_r0 * K + a_c0 * 8);
        cp16(smA_u + a_r1 * (APAD * 2) + a_c1 * 16, Ab + (size_t)a_r1 * K + a_c1 * 8);
        cp16(smB_u + b_r0 * (BPAD * 2) + b_c0 * 16, Bb + (size_t)b_r0 * N + b_c0 * 8);
        cp16(smB_u + b_r1 * (BPAD * 2) + b_c1 * 16, Bb + (size_t)b_r1 * N + b_c1 * 8);
        asm volatile("cp.async.commit_group;" ::: "memory");
    }

    for (int kt = 0; kt < ntiles; ++kt) {
        const int s = kt & 1;
        if (kt + 1 < ntiles) {
            const int k0 = (kt + 1) * GBK;
            const uint32_t aB = smA_u + (s ^ 1) * ASTG_B;
            const uint32_t bB = smB_u + (s ^ 1) * BSTG_B;
            cp16(aB + a_r0 * (APAD * 2) + a_c0 * 16, Ab + (size_t)a_r0 * K + k0 + a_c0 * 8);
            cp16(aB + a_r1 * (APAD * 2) + a_c1 * 16, Ab + (size_t)a_r1 * K + k0 + a_c1 * 8);
            cp16(bB + b_r0 * (BPAD * 2) + b_c0 * 16, Bb + (size_t)(k0 + b_r0) * N + b_c0 * 8);
            cp16(bB + b_r1 * (BPAD * 2) + b_c1 * 16, Bb + (size_t)(k0 + b_r1) * N + b_c1 * 8);
            asm volatile("cp.async.commit_group;" ::: "memory");
            asm volatile("cp.async.wait_group 1;" ::: "memory");
        } else {
            asm volatile("cp.async.wait_group 0;" ::: "memory");
        }
        __syncthreads();

        const uint32_t aS = smA_u + s * ASTG_B;
        const uint32_t bS = smB_u + s * BSTG_B;

        #pragma unroll
        for (int ks = 0; ks < 2; ++ks) {
            uint32_t a[4][4], bfr[4][2];
            #pragma unroll
            for (int mf = 0; mf < 4; ++mf) {
                uint32_t addr = aS
                    + (uint32_t)(wm + mf * 16 + (lane & 15)) * (APAD * 2)
                    + (uint32_t)(ks * 16 + ((lane >> 4) << 3)) * 2;
                ldsm_x4(a[mf][0], a[mf][1], a[mf][2], a[mf][3], addr);
            }
            #pragma unroll
            for (int nf = 0; nf < 4; ++nf) {
                uint32_t addr = bS
                    + (uint32_t)(ks * 16 + (lane & 15)) * (BPAD * 2)
                    + (uint32_t)(wn + nf * 8) * 2;
                ldsm_x2t(bfr[nf][0], bfr[nf][1], addr);
            }
            #pragma unroll
            for (int mf = 0; mf < 4; ++mf)
                #pragma unroll
                for (int nf = 0; nf < 4; ++nf)
                    MMA_F16(acc[mf][nf][0], acc[mf][nf][1],
                            acc[mf][nf][2], acc[mf][nf][3],
                            a[mf][0], a[mf][1], a[mf][2], a[mf][3],
                            bfr[nf][0], bfr[nf][1]);
        }
        __syncthreads();
    }

    // epilogue
    #pragma unroll
    for (int mf = 0; mf < 4; ++mf) {
        const int row = m0 + wm + mf * 16 + g;
        #pragma unroll
        for (int nf = 0; nf < 4; ++nf) {
            const int col = n0 + wn + nf * 8 + 2 * t;
            float2 b2 = *reinterpret_cast<const float2*>(bias + col);
            float o00 = acc[mf][nf][0] + b2.x, o01 = acc[mf][nf][1] + b2.y;
            float o10 = acc[mf][nf][2] + b2.x, o11 = acc[mf][nf][3] + b2.y;
            if (sizeof(OutT) == 2) {
                __half* p0 = (__half*)C + (size_t)row * N + col;
                __half* p1 = (__half*)C + (size_t)(row + 8) * N + col;
                *reinterpret_cast<uint32_t*>(p0) = ph2(o00, o01);
                *reinterpret_cast<uint32_t*>(p1) = ph2(o10, o11);
            } else {
                float* p0 = (float*)C + (size_t)row * N + col;
                float* p1 = (float*)C + (size_t)(row + 8) * N + col;
                *reinterpret_cast<float2*>(p0) = make_float2(o00, o01);
                *reinterpret_cast<float2*>(p1) = make_float2(o10, o11);
            }
        }
    }
}

// ---------------------------------------------------------------------------
// f16 tensor-core causal flash attention; qkv input f16, output f16.
// CTA: 128 threads / 4 warps; 64-query tile; 64-key K/V smem tiles.
// ---------------------------------------------------------------------------
#define KSTH 72    // halves per smem row (64 + 8 pad); 144B stride

__global__ __launch_bounds__(128)
void attn_f16(__half* __restrict__ out)
{
    __shared__ __align__(16) __half Ks[64][KSTH];
    __shared__ __align__(16) __half Vs[64][KSTH];

    const int b  = blockIdx.z;
    const int h  = blockIdx.y;
    const int qt = blockIdx.x;
    const int tid  = threadIdx.x;
    const int w    = tid >> 5;
    const int lane = tid & 31;
    const int g = lane >> 2;
    const int t = lane & 3;
    const int q0 = qt * 64;

    const size_t row3E = (size_t)3 * EMB;
    const __half* basep = g_qkvh + (size_t)b * SEQ * row3E;

    // Q fragments (f16x2, pre-scaled by 1/8 — exact)
    uint32_t qa[4][4];
    {
        const __half2 sc = __half2half2(__float2half_rn(0.125f));
        const __half* q0p = basep + (size_t)(q0 + w * 16 + g) * row3E + h * HDIM;
        const __half* q8p = q0p + 8 * row3E;
        #pragma unroll
        for (int ks = 0; ks < 4; ++ks) {
            __half2 v0 = *reinterpret_cast<const __half2*>(q0p + ks * 16 + 2 * t);
            __half2 v1 = *reinterpret_cast<const __half2*>(q8p + ks * 16 + 2 * t);
            __half2 v2 = *reinterpret_cast<const __half2*>(q0p + ks * 16 + 8 + 2 * t);
            __half2 v3 = *reinterpret_cast<const __half2*>(q8p + ks * 16 + 8 + 2 * t);
            v0 = __hmul2(v0, sc); v1 = __hmul2(v1, sc);
            v2 = __hmul2(v2, sc); v3 = __hmul2(v3, sc);
            qa[ks][0] = *reinterpret_cast<uint32_t*>(&v0);
            qa[ks][1] = *reinterpret_cast<uint32_t*>(&v1);
            qa[ks][2] = *reinterpret_cast<uint32_t*>(&v2);
            qa[ks][3] = *reinterpret_cast<uint32_t*>(&v3);
        }
    }

    float m0 = -INFINITY, m1 = -INFINITY, l0 = 0.f, l1 = 0.f;
    float o[8][4];
    #pragma unroll
    for (int nf = 0; nf < 8; ++nf)
        #pragma unroll
        for (int c = 0; c < 4; ++c) o[nf][c] = 0.f;

    const uint32_t ksu = s2u(Ks);
    const uint32_t vsu = s2u(Vs);
    const int krow = lane & 7;
    const int khalf = (lane >> 3) & 1;
    const int vrow = lane & 15;

    for (int k0 = 0; k0 <= q0; k0 += 64) {
        __syncthreads();
        // K/V tile copy (f16, 16B vectors)
        #pragma unroll
        for (int i = 0; i < 4; ++i) {
            int idx = tid + i * 128;       // 0..511
            int r = idx >> 3;              // 0..63
            int c = (idx & 7) << 3;        // 0..56
            const __half* rowp = basep + (size_t)(k0 + r) * row3E + h * HDIM + c;
            *reinterpret_cast<uint4*>(&Ks[r][c]) =
                *reinterpret_cast<const uint4*>(rowp + EMB);
            *reinterpret_cast<uint4*>(&Vs[r][c]) =
                *reinterpret_cast<const uint4*>(rowp + 2 * EMB);
        }
        __syncthreads();

        // scores
        float s[8][4];
        #pragma unroll
        for (int nf = 0; nf < 8; ++nf)
            #pragma unroll
            for (int c = 0; c < 4; ++c) s[nf][c] = 0.f;

        #pragma unroll
        for (int nf = 0; nf < 8; ++nf) {
            #pragma unroll
            for (int ks = 0; ks < 4; ++ks) {
                uint32_t b0, b1;
                uint32_t addr = ksu + (uint32_t)(nf * 8 + krow) * (KSTH * 2)
                              + (uint32_t)(ks * 16 + khalf * 8) * 2;
                ldsm_x2(b0, b1, addr);
                MMA_F16(s[nf][0], s[nf][1], s[nf][2], s[nf][3],
                        qa[ks][0], qa[ks][1], qa[ks][2], qa[ks][3], b0, b1);
            }
        }

        // causal mask (diagonal tile)
        if (k0 == q0) {
            const int r0l = w * 16 + g;
            #pragma unroll
            for (int nf = 0; nf < 8; ++nf) {
                const int c0 = nf * 8 + 2 * t;
                if (c0     > r0l)     s[nf][0] = -INFINITY;
                if (c0 + 1 > r0l)     s[nf][1] = -INFINITY;
                if (c0     > r0l + 8) s[nf][2] = -INFINITY;
                if (c0 + 1 > r0l + 8) s[nf][3] = -INFINITY;
            }
        }

        // online softmax
        float tm0 = -INFINITY, tm1 = -INFINITY;
        #pragma unroll
        for (int nf = 0; nf < 8; ++nf) {
            tm0 = fmaxf(tm0, fmaxf(s[nf][0], s[nf][1]));
            tm1 = fmaxf(tm1, fmaxf(s[nf][2], s[nf][3]));
        }
        tm0 = fmaxf(tm0, __shfl_xor_sync(0xffffffffu, tm0, 1));
        tm0 = fmaxf(tm0, __shfl_xor_sync(0xffffffffu, tm0, 2));
        tm1 = fmaxf(tm1, __shfl_xor_sync(0xffffffffu, tm1, 1));
        tm1 = fmaxf(tm1, __shfl_xor_sync(0xffffffffu, tm1, 2));

        const float m0n = fmaxf(m0, tm0);
        const float m1n = fmaxf(m1, tm1);
        const float c0 = __expf(m0 - m0n);
        const float c1 = __expf(m1 - m1n);
        m0 = m0n; m1 = m1n;

        float ls0 = 0.f, ls1 = 0.f;
        #pragma unroll
        for (int nf = 0; nf < 8; ++nf) {
            s[nf][0] = __expf(s[nf][0] - m0n); ls0 += s[nf][0];
            s[nf][1] = __expf(s[nf][1] - m0n); ls0 += s[nf][1];
            s[nf][2] = __expf(s[nf][2] - m1n); ls1 += s[nf][2];
            s[nf][3] = __expf(s[nf][3] - m1n); ls1 += s[nf][3];
        }
        ls0 += __shfl_xor_sync(0xffffffffu, ls0, 1);
        ls0 += __shfl_xor_sync(0xffffffffu, ls0, 2);
        ls1 += __shfl_xor_sync(0xffffffffu, ls1, 1);
        ls1 += __shfl_xor_sync(0xffffffffu, ls1, 2);
        l0 = l0 * c0 + ls0;
        l1 = l1 * c1 + ls1;

        #pragma unroll
        for (int nf = 0; nf < 8; ++nf) {
            o[nf][0] *= c0; o[nf][1] *= c0;
            o[nf][2] *= c1; o[nf][3] *= c1;
        }

        // P -> f16 A-fragments in registers
        uint32_t pa[4][4];
        #pragma unroll
        for (int ks = 0; ks < 4; ++ks) {
            pa[ks][0] = ph2(s[2 * ks][0],     s[2 * ks][1]);
            pa[ks][1] = ph2(s[2 * ks][2],     s[2 * ks][3]);
            pa[ks][2] = ph2(s[2 * ks + 1][0], s[2 * ks + 1][1]);
            pa[ks][3] = ph2(s[2 * ks + 1][2], s[2 * ks + 1][3]);
        }

        // O += P @ V
        #pragma unroll
        for (int nf = 0; nf < 8; ++nf) {
            #pragma unroll
            for (int ks = 0; ks < 4; ++ks) {
                uint32_t v0, v1;
                uint32_t addr = vsu + (uint32_t)(ks * 16 + vrow) * (KSTH * 2)
                              + (uint32_t)nf * 16;
                ldsm_x2t(v0, v1, addr);
                MMA_F16(o[nf][0], o[nf][1], o[nf][2], o[nf][3],
                        pa[ks][0], pa[ks][1], pa[ks][2], pa[ks][3], v0, v1);
            }
        }
    }

    // epilogue -> f16
    const float inv0 = 1.f / l0;
    const float inv1 = 1.f / l1;
    const int gr0 = q0 + w * 16 + g;
    __half* op0 = out + ((size_t)b * SEQ + gr0) * EMB + h * HDIM;
    __half* op1 = op0 + 8 * EMB;
    #pragma unroll
    for (int nf = 0; nf < 8; ++nf) {
        const int col = nf * 8 + 2 * t;
        *reinterpret_cast<uint32_t*>(op0 + col) = ph2(o[nf][0] * inv0, o[nf][1] * inv0);
        *reinterpret_cast<uint32_t*>(op1 + col) = ph2(o[nf][2] * inv1, o[nf][3] * inv1);
    }
}

// ---------------------------------------------------------------------------
// Launch
// ---------------------------------------------------------------------------
extern "C" void kernel_launch(void* const* d_in, const int* in_sizes, int n_in,
                              void* d_out, int out_size)
{
    (void)in_sizes; (void)n_in; (void)out_size;
    const float* x     = (const float*)d_in[0];
    const float* W_qkv = (const float*)d_in[1];
    const float* b_qkv = (const float*)d_in[2];
    const float* W_o   = (const float*)d_in[3];
    const float* b_o   = (const float*)d_in[4];
    float* out = (float*)d_out;

    __half *xh = nullptr, *wqkvh = nullptr, *woh = nullptr;
    __half *qkvh = nullptr, *attnh = nullptr;
    cudaGetSymbolAddress((void**)&xh,    g_xh);
    cudaGetSymbolAddress((void**)&wqkvh, g_wqkvh);
    cudaGetSymbolAddress((void**)&woh,   g_woh);
    cudaGetSymbolAddress((void**)&qkvh,  g_qkvh);
    cudaGetSymbolAddress((void**)&attnh, g_attnh);

    cudaFuncSetAttribute(gemm_f16<__half>,
                         cudaFuncAttributeMaxDynamicSharedMemorySize, GSMEM);
    cudaFuncSetAttribute(gemm_f16<float>,
                         cudaFuncAttributeMaxDynamicSharedMemorySize, GSMEM);

    // 0) pre-pass conversions
    f32_to_f16<<<(M_ROWS * EMB / 4 + 255) / 256, 256>>>(x, xh, M_ROWS * EMB / 4);
    f32_to_f16<<<(3 * EMB * EMB / 4 + 255) / 256, 256>>>(W_qkv, wqkvh, 3 * EMB * EMB / 4);
    f32_to_f16<<<(EMB * EMB / 4 + 255) / 256, 256>>>(W_o, woh, EMB * EMB / 4);

    // 1) QKV projection (f16 out)
    gemm_f16<__half><<<dim3(3 * EMB / GBN, M_ROWS / GBM), 256, GSMEM>>>(
        xh, wqkvh, b_qkv, qkvh, M_ROWS, 3 * EMB, EMB);

    // 2) f16 causal flash attention
    attn_f16<<<dim3(SEQ / 64, HEADS, BATCH), 128>>>(attnh);

    // 3) Output projection (f32 out)
    gemm_f16<float><<<dim3(EMB / GBN, M_ROWS / GBM), 256, GSMEM>>>(
        attnh, woh, b_o, out, M_ROWS, EMB, EMB);
}

// round 8
// speedup vs baseline: 8.1485x; 1.0159x over previous
#include <cuda_runtime.h>
#include <cuda_fp16.h>
#include <math.h>
#include <stdint.h>
#include <stddef.h>

// Problem constants
#define BATCH 4
#define SEQ   2048
#define EMB   1024
#define HEADS 16
#define HDIM  64
#define M_ROWS (BATCH*SEQ)   // 8192

// Scratch (device globals — allocation-free per harness rules)
__device__ __half g_xh[(size_t)M_ROWS * EMB];        // x f16
__device__ __half g_wqkvh[(size_t)EMB * 3 * EMB];    // W_qkv f16 [K,N]
__device__ __half g_woh[(size_t)EMB * EMB];          // W_o f16 [K,N]
__device__ __half g_qkvh[(size_t)M_ROWS * 3 * EMB];  // qkv f16
__device__ __half g_attnh[(size_t)M_ROWS * EMB];     // attention out f16

// ---------------------------------------------------------------------------
// Helpers
// ---------------------------------------------------------------------------
__device__ __forceinline__ uint32_t ph2(float a, float b) {
    __half2 h = __floats2half2_rn(a, b);
    return *reinterpret_cast<uint32_t*>(&h);
}
__device__ __forceinline__ uint32_t s2u(const void* p) {
    uint32_t r;
    asm("{ .reg .u64 t; cvta.to.shared.u64 t, %1; cvt.u32.u64 %0, t; }"
        : "=r"(r) : "l"(p));
    return r;
}

#define MMA_F16(d0,d1,d2,d3, a0,a1,a2,a3, b0,b1)                            \
    asm volatile(                                                           \
        "mma.sync.aligned.m16n8k16.row.col.f32.f16.f16.f32 "                \
        "{%0,%1,%2,%3}, {%4,%5,%6,%7}, {%8,%9}, {%0,%1,%2,%3};"             \
        : "+f"(d0), "+f"(d1), "+f"(d2), "+f"(d3)                            \
        : "r"(a0), "r"(a1), "r"(a2), "r"(a3), "r"(b0), "r"(b1))

__device__ __forceinline__ void ldsm_x4(uint32_t& r0, uint32_t& r1,
                                        uint32_t& r2, uint32_t& r3, uint32_t addr) {
    asm volatile("ldmatrix.sync.aligned.m8n8.x4.shared.b16 {%0,%1,%2,%3}, [%4];"
                 : "=r"(r0), "=r"(r1), "=r"(r2), "=r"(r3) : "r"(addr));
}
__device__ __forceinline__ void ldsm_x4t(uint32_t& r0, uint32_t& r1,
                                         uint32_t& r2, uint32_t& r3, uint32_t addr) {
    asm volatile("ldmatrix.sync.aligned.m8n8.x4.trans.shared.b16 {%0,%1,%2,%3}, [%4];"
                 : "=r"(r0), "=r"(r1), "=r"(r2), "=r"(r3) : "r"(addr));
}
__device__ __forceinline__ void cp16(uint32_t dst, const void* src) {
    asm volatile("cp.async.cg.shared.global [%0], [%1], 16;"
                 :: "r"(dst), "l"(src) : "memory");
}
#define CP_COMMIT() asm volatile("cp.async.commit_group;" ::: "memory")
#define CP_WAIT(n)  asm volatile("cp.async.wait_group %0;" :: "n"(n) : "memory")

// ---------------------------------------------------------------------------
// Pre-pass: f32 -> f16
// ---------------------------------------------------------------------------
__global__ __launch_bounds__(256)
void f32_to_f16(const float* __restrict__ in, __half* __restrict__ out, int n4) {
    int i = blockIdx.x * 256 + threadIdx.x;
    if (i < n4) {
        float4 v = reinterpret_cast<const float4*>(in)[i];
        uint2 o = make_uint2(ph2(v.x, v.y), ph2(v.z, v.w));
        reinterpret_cast<uint2*>(out)[i] = o;
    }
}

// ---------------------------------------------------------------------------
// f16 tensor-core GEMM: C[M,N] = A[M,K] @ B[K,N] + bias
// CTA 128x128x32, 256 threads / 8 warps, warp tile 64x32.
// 3-stage cp.async pipeline, one __syncthreads per K chunk.
// ---------------------------------------------------------------------------
#define GBM 128
#define GBN 128
#define GBK 32
#define APAD 40
#define BPAD 136
#define ASTG_B (GBM * APAD * 2)    // 10240 B
#define BSTG_B (GBK * BPAD * 2)    // 8704 B
#define NSTG 3
#define GSMEM (NSTG * (ASTG_B + BSTG_B))   // 56832 B

template <typename OutT>
__global__ __launch_bounds__(256)
void gemm_f16(const __half* __restrict__ A, const __half* __restrict__ B,
              const float* __restrict__ bias, OutT* __restrict__ C,
              int M, int N, int K)
{
    extern __shared__ __align__(16) char smem[];
    const int tid  = threadIdx.x;
    const int wid  = tid >> 5;
    const int lane = tid & 31;
    const int g = lane >> 2;
    const int t = lane & 3;
    const int wm = (wid >> 2) * 64;
    const int wn = (wid & 3) * 32;
    const int n0 = blockIdx.x * GBN;
    const int m0 = blockIdx.y * GBM;

    const uint32_t smA_u = s2u(smem);
    const uint32_t smB_u = smA_u + NSTG * ASTG_B;

    const __half* Ab = A + (size_t)m0 * K;
    const __half* Bb = B + n0;

    float acc[4][4][4];
    #pragma unroll
    for (int i = 0; i < 4; ++i)
        #pragma unroll
        for (int j = 0; j < 4; ++j)
            #pragma unroll
            for (int c = 0; c < 4; ++c) acc[i][j][c] = 0.f;

    const int a_r0 = tid >> 2,         a_c0 = (tid & 3);
    const int a_r1 = (tid + 256) >> 2, a_c1 = ((tid + 256) & 3);
    const int b_r0 = tid >> 4,         b_c0 = (tid & 15);
    const int b_r1 = (tid + 256) >> 4, b_c1 = ((tid + 256) & 15);

    const int ntiles = K / GBK;

    #define LOAD_CHUNK(kc, st) do {                                              \
        const int _k0 = (kc) * GBK;                                              \
        const uint32_t _aB = smA_u + (st) * ASTG_B;                              \
        const uint32_t _bB = smB_u + (st) * BSTG_B;                              \
        cp16(_aB + a_r0 * (APAD * 2) + a_c0 * 16, Ab + (size_t)a_r0 * K + _k0 + a_c0 * 8); \
        cp16(_aB + a_r1 * (APAD * 2) + a_c1 * 16, Ab + (size_t)a_r1 * K + _k0 + a_c1 * 8); \
        cp16(_bB + b_r0 * (BPAD * 2) + b_c0 * 16, Bb + (size_t)(_k0 + b_r0) * N + b_c0 * 8); \
        cp16(_bB + b_r1 * (BPAD * 2) + b_c1 * 16, Bb + (size_t)(_k0 + b_r1) * N + b_c1 * 8); \
        CP_COMMIT();                                                             \
    } while (0)

    // prologue: 2 chunks in flight
    LOAD_CHUNK(0, 0);
    if (ntiles > 1) LOAD_CHUNK(1, 1);

    int st = 0;
    for (int kt = 0; kt < ntiles; ++kt) {
        if (kt + 1 < ntiles) { CP_WAIT(1); } else { CP_WAIT(0); }
        __syncthreads();   // all warps done with stage (kt+2)%NSTG's old data
        if (kt + 2 < ntiles) {
            int st2 = st + 2; if (st2 >= NSTG) st2 -= NSTG;
            LOAD_CHUNK(kt + 2, st2);
        }

        const uint32_t aS = smA_u + st * ASTG_B;
        const uint32_t bS = smB_u + st * BSTG_B;

        #pragma unroll
        for (int ks = 0; ks < 2; ++ks) {
            uint32_t a[4][4], bfr[4][2];
            #pragma unroll
            for (int mf = 0; mf < 4; ++mf) {
                uint32_t addr = aS
                    + (uint32_t)(wm + mf * 16 + (lane & 15)) * (APAD * 2)
                    + (uint32_t)(ks * 16 + ((lane >> 4) << 3)) * 2;
                ldsm_x4(a[mf][0], a[mf][1], a[mf][2], a[mf][3], addr);
            }
            #pragma unroll
            for (int p = 0; p < 2; ++p) {   // nf pairs (0,1) and (2,3)
                uint32_t addr = bS
                    + (uint32_t)(ks * 16 + (lane & 15)) * (BPAD * 2)
                    + (uint32_t)(wn + p * 16 + ((lane >> 4) << 3)) * 2;
                ldsm_x4t(bfr[2 * p][0], bfr[2 * p][1],
                         bfr[2 * p + 1][0], bfr[2 * p + 1][1], addr);
            }
            #pragma unroll
            for (int mf = 0; mf < 4; ++mf)
                #pragma unroll
                for (int nf = 0; nf < 4; ++nf)
                    MMA_F16(acc[mf][nf][0], acc[mf][nf][1],
                            acc[mf][nf][2], acc[mf][nf][3],
                            a[mf][0], a[mf][1], a[mf][2], a[mf][3],
                            bfr[nf][0], bfr[nf][1]);
        }
        if (++st >= NSTG) st -= NSTG;
    }
    #undef LOAD_CHUNK

    // epilogue
    #pragma unroll
    for (int mf = 0; mf < 4; ++mf) {
        const int row = m0 + wm + mf * 16 + g;
        #pragma unroll
        for (int nf = 0; nf < 4; ++nf) {
            const int col = n0 + wn + nf * 8 + 2 * t;
            float2 b2 = *reinterpret_cast<const float2*>(bias + col);
            float o00 = acc[mf][nf][0] + b2.x, o01 = acc[mf][nf][1] + b2.y;
            float o10 = acc[mf][nf][2] + b2.x, o11 = acc[mf][nf][3] + b2.y;
            if (sizeof(OutT) == 2) {
                __half* p0 = (__half*)C + (size_t)row * N + col;
                __half* p1 = (__half*)C + (size_t)(row + 8) * N + col;
                *reinterpret_cast<uint32_t*>(p0) = ph2(o00, o01);
                *reinterpret_cast<uint32_t*>(p1) = ph2(o10, o11);
            } else {
                float* p0 = (float*)C + (size_t)row * N + col;
                float* p1 = (float*)C + (size_t)(row + 8) * N + col;
                *reinterpret_cast<float2*>(p0) = make_float2(o00, o01);
                *reinterpret_cast<float2*>(p1) = make_float2(o10, o11);
            }
        }
    }
}

// ---------------------------------------------------------------------------
// f16 causal flash attention; cp.async double-buffered K/V, x4 ldmatrix.
// CTA: 128 threads / 4 warps; 64-query tile; 64-key K/V tiles.
// ---------------------------------------------------------------------------
#define KSTH 72                      // halves per row (64 + 8 pad) -> 144 B
#define KROW_B (KSTH * 2)            // 144
#define KTILE_B (64 * KROW_B)        // 9216 per matrix
#define ASTAGE_B (2 * KTILE_B)       // K + V per stage: 18432
#define ASMEM (2 * ASTAGE_B)         // 36864

__global__ __launch_bounds__(128)
void attn_f16(__half* __restrict__ out)
{
    extern __shared__ __align__(16) char asmem[];
    const int b  = blockIdx.z;
    const int h  = blockIdx.y;
    const int qt = blockIdx.x;
    const int tid  = threadIdx.x;
    const int w    = tid >> 5;
    const int lane = tid & 31;
    const int g = lane >> 2;
    const int t = lane & 3;
    const int q0 = qt * 64;

    const size_t row3E = (size_t)3 * EMB;
    const __half* basep = g_qkvh + (size_t)b * SEQ * row3E;
    const uint32_t smu = s2u(asmem);

    // Q fragments (f16x2, pre-scaled by 1/8 — exact in f16)
    uint32_t qa[4][4];
    {
        const __half2 sc = __half2half2(__float2half_rn(0.125f));
        const __half* q0p = basep + (size_t)(q0 + w * 16 + g) * row3E + h * HDIM;
        const __half* q8p = q0p + 8 * row3E;
        #pragma unroll
        for (int ks = 0; ks < 4; ++ks) {
            __half2 v0 = *reinterpret_cast<const __half2*>(q0p + ks * 16 + 2 * t);
            __half2 v1 = *reinterpret_cast<const __half2*>(q8p + ks * 16 + 2 * t);
            __half2 v2 = *reinterpret_cast<const __half2*>(q0p + ks * 16 + 8 + 2 * t);
            __half2 v3 = *reinterpret_cast<const __half2*>(q8p + ks * 16 + 8 + 2 * t);
            v0 = __hmul2(v0, sc); v1 = __hmul2(v1, sc);
            v2 = __hmul2(v2, sc); v3 = __hmul2(v3, sc);
            qa[ks][0] = *reinterpret_cast<uint32_t*>(&v0);
            qa[ks][1] = *reinterpret_cast<uint32_t*>(&v1);
            qa[ks][2] = *reinterpret_cast<uint32_t*>(&v2);
            qa[ks][3] = *reinterpret_cast<uint32_t*>(&v3);
        }
    }

    float m0 = -INFINITY, m1 = -INFINITY, l0 = 0.f, l1 = 0.f;
    float o[8][4];
    #pragma unroll
    for (int nf = 0; nf < 8; ++nf)
        #pragma unroll
        for (int c = 0; c < 4; ++c) o[nf][c] = 0.f;

    // tile loader: K and V, 64 rows x 128 B each, 4 cp16 per thread per matrix
    #define LOAD_TILE(kt_, st_) do {                                             \
        const int _k0 = (kt_) * 64;                                              \
        const uint32_t _kB = smu + (st_) * ASTAGE_B;                             \
        const uint32_t _vB = _kB + KTILE_B;                                      \
        _Pragma("unroll")                                                        \
        for (int _i = 0; _i < 4; ++_i) {                                         \
            int _idx = tid + _i * 128;                                           \
            int _r = _idx >> 3;                                                  \
            int _cb = (_idx & 7) << 4;                                           \
            const __half* _rp = basep + (size_t)(_k0 + _r) * row3E + h * HDIM;   \
            cp16(_kB + _r * KROW_B + _cb, (const char*)(_rp + EMB) + _cb);       \
            cp16(_vB + _r * KROW_B + _cb, (const char*)(_rp + 2 * EMB) + _cb);   \
        }                                                                        \
        CP_COMMIT();                                                             \
    } while (0)

    const int ntile = q0 / 64 + 1;
    LOAD_TILE(0, 0);

    // ldmatrix lane addressing
    const int kq_row = lane & 7;                // within-pair row
    const int kq_sel = (lane >> 4) & 1;         // nf-pair select
    const int kq_col = (lane >> 3) & 1;         // k-half select
    const int v_row = lane & 15;
    const int v_sel = (lane >> 4) & 1;

    for (int kt = 0; kt < ntile; ++kt) {
        const int st = kt & 1;
        if (kt + 1 < ntile) { CP_WAIT(1); } else { CP_WAIT(0); }
        __syncthreads();
        if (kt + 1 < ntile) LOAD_TILE(kt + 1, st ^ 1);

        const uint32_t kB = smu + st * ASTAGE_B;
        const uint32_t vB = kB + KTILE_B;

        // scores: S[16x64] = Q @ K^T  — x4 loads cover 2 nf at once
        float s[8][4];
        #pragma unroll
        for (int nf = 0; nf < 8; ++nf)
            #pragma unroll
            for (int c = 0; c < 4; ++c) s[nf][c] = 0.f;

        #pragma unroll
        for (int p = 0; p < 4; ++p) {       // nf pairs
            uint32_t bf[2][2];
            #pragma unroll
            for (int ks = 0; ks < 4; ++ks) {
                uint32_t addr = kB
                    + (uint32_t)((2 * p + kq_sel) * 8 + kq_row) * KROW_B
                    + (uint32_t)(ks * 16 + kq_col * 8) * 2;
                ldsm_x4(bf[0][0], bf[0][1], bf[1][0], bf[1][1], addr);
                MMA_F16(s[2*p][0], s[2*p][1], s[2*p][2], s[2*p][3],
                        qa[ks][0], qa[ks][1], qa[ks][2], qa[ks][3],
                        bf[0][0], bf[0][1]);
                MMA_F16(s[2*p+1][0], s[2*p+1][1], s[2*p+1][2], s[2*p+1][3],
                        qa[ks][0], qa[ks][1], qa[ks][2], qa[ks][3],
                        bf[1][0], bf[1][1]);
            }
        }

        // causal mask (diagonal tile)
        if (kt == ntile - 1) {
            const int r0l = w * 16 + g;
            #pragma unroll
            for (int nf = 0; nf < 8; ++nf) {
                const int c0 = nf * 8 + 2 * t;
                if (c0     > r0l)     s[nf][0] = -INFINITY;
                if (c0 + 1 > r0l)     s[nf][1] = -INFINITY;
                if (c0     > r0l + 8) s[nf][2] = -INFINITY;
                if (c0 + 1 > r0l + 8) s[nf][3] = -INFINITY;
            }
        }

        // online softmax
        float tm0 = -INFINITY, tm1 = -INFINITY;
        #pragma unroll
        for (int nf = 0; nf < 8; ++nf) {
            tm0 = fmaxf(tm0, fmaxf(s[nf][0], s[nf][1]));
            tm1 = fmaxf(tm1, fmaxf(s[nf][2], s[nf][3]));
        }
        tm0 = fmaxf(tm0, __shfl_xor_sync(0xffffffffu, tm0, 1));
        tm0 = fmaxf(tm0, __shfl_xor_sync(0xffffffffu, tm0, 2));
        tm1 = fmaxf(tm1, __shfl_xor_sync(0xffffffffu, tm1, 1));
        tm1 = fmaxf(tm1, __shfl_xor_sync(0xffffffffu, tm1, 2));

        const float m0n = fmaxf(m0, tm0);
        const float m1n = fmaxf(m1, tm1);
        const float c0 = __expf(m0 - m0n);
        const float c1 = __expf(m1 - m1n);
        m0 = m0n; m1 = m1n;

        float ls0 = 0.f, ls1 = 0.f;
        #pragma unroll
        for (int nf = 0; nf < 8; ++nf) {
            s[nf][0] = __expf(s[nf][0] - m0n); ls0 += s[nf][0];
            s[nf][1] = __expf(s[nf][1] - m0n); ls0 += s[nf][1];
            s[nf][2] = __expf(s[nf][2] - m1n); ls1 += s[nf][2];
            s[nf][3] = __expf(s[nf][3] - m1n); ls1 += s[nf][3];
        }
        ls0 += __shfl_xor_sync(0xffffffffu, ls0, 1);
        ls0 += __shfl_xor_sync(0xffffffffu, ls0, 2);
        ls1 += __shfl_xor_sync(0xffffffffu, ls1, 1);
        ls1 += __shfl_xor_sync(0xffffffffu, ls1, 2);
        l0 = l0 * c0 + ls0;
        l1 = l1 * c1 + ls1;

        #pragma unroll
        for (int nf = 0; nf < 8; ++nf) {
            o[nf][0] *= c0; o[nf][1] *= c0;
            o[nf][2] *= c1; o[nf][3] *= c1;
        }

        // P -> f16 A-fragments in registers
        uint32_t pa[4][4];
        #pragma unroll
        for (int ks = 0; ks < 4; ++ks) {
            pa[ks][0] = ph2(s[2 * ks][0],     s[2 * ks][1]);
            pa[ks][1] = ph2(s[2 * ks][2],     s[2 * ks][3]);
            pa[ks][2] = ph2(s[2 * ks + 1][0], s[2 * ks + 1][1]);
            pa[ks][3] = ph2(s[2 * ks + 1][2], s[2 * ks + 1][3]);
        }

        // O += P @ V — x4.trans covers 2 nf at once
        #pragma unroll
        for (int p = 0; p < 4; ++p) {
            #pragma unroll
            for (int ks = 0; ks < 4; ++ks) {
                uint32_t v0, v1, v2, v3;
                uint32_t addr = vB
                    + (uint32_t)(ks * 16 + v_row) * KROW_B
                    + (uint32_t)((2 * p + v_sel) * 8) * 2;
                ldsm_x4t(v0, v1, v2, v3, addr);
                MMA_F16(o[2*p][0], o[2*p][1], o[2*p][2], o[2*p][3],
                        pa[ks][0], pa[ks][1], pa[ks][2], pa[ks][3], v0, v1);
                MMA_F16(o[2*p+1][0], o[2*p+1][1], o[2*p+1][2], o[2*p+1][3],
                        pa[ks][0], pa[ks][1], pa[ks][2], pa[ks][3], v2, v3);
            }
        }
    }
    #undef LOAD_TILE

    // epilogue -> f16
    const float inv0 = 1.f / l0;
    const float inv1 = 1.f / l1;
    const int gr0 = q0 + w * 16 + g;
    __half* op0 = out + ((size_t)b * SEQ + gr0) * EMB + h * HDIM;
    __half* op1 = op0 + 8 * EMB;
    #pragma unroll
    for (int nf = 0; nf < 8; ++nf) {
        const int col = nf * 8 + 2 * t;
        *reinterpret_cast<uint32_t*>(op0 + col) = ph2(o[nf][0] * inv0, o[nf][1] * inv0);
        *reinterpret_cast<uint32_t*>(op1 + col) = ph2(o[nf][2] * inv1, o[nf][3] * inv1);
    }
}

// ---------------------------------------------------------------------------
// Launch
// ---------------------------------------------------------------------------
extern "C" void kernel_launch(void* const* d_in, const int* in_sizes, int n_in,
                              void* d_out, int out_size)
{
    (void)in_sizes; (void)n_in; (void)out_size;
    const float* x     = (const float*)d_in[0];
    const float* W_qkv = (const float*)d_in[1];
    const float* b_qkv = (const float*)d_in[2];
    const float* W_o   = (const float*)d_in[3];
    const float* b_o   = (const float*)d_in[4];
    float* out = (float*)d_out;

    __half *xh = nullptr, *wqkvh = nullptr, *woh = nullptr;
    __half *qkvh = nullptr, *attnh = nullptr;
    cudaGetSymbolAddress((void**)&xh,    g_xh);
    cudaGetSymbolAddress((void**)&wqkvh, g_wqkvh);
    cudaGetSymbolAddress((void**)&woh,   g_woh);
    cudaGetSymbolAddress((void**)&qkvh,  g_qkvh);
    cudaGetSymbolAddress((void**)&attnh, g_attnh);

    cudaFuncSetAttribute(gemm_f16<__half>,
                         cudaFuncAttributeMaxDynamicSharedMemorySize, GSMEM);
    cudaFuncSetAttribute(gemm_f16<float>,
                         cudaFuncAttributeMaxDynamicSharedMemorySize, GSMEM);

    // 0) pre-pass conversions
    f32_to_f16<<<(M_ROWS * EMB / 4 + 255) / 256, 256>>>(x, xh, M_ROWS * EMB / 4);
    f32_to_f16<<<(3 * EMB * EMB / 4 + 255) / 256, 256>>>(W_qkv, wqkvh, 3 * EMB * EMB / 4);
    f32_to_f16<<<(EMB * EMB / 4 + 255) / 256, 256>>>(W_o, woh, EMB * EMB / 4);

    // 1) QKV projection (f16 out)
    gemm_f16<__half><<<dim3(3 * EMB / GBN, M_ROWS / GBM), 256, GSMEM>>>(
        xh, wqkvh, b_qkv, qkvh, M_ROWS, 3 * EMB, EMB);

    // 2) f16 causal flash attention
    attn_f16<<<dim3(SEQ / 64, HEADS, BATCH), 128, ASMEM>>>(attnh);

    // 3) Output projection (f32 out)
    gemm_f16<float><<<dim3(EMB / GBN, M_ROWS / GBM), 256, GSMEM>>>(
        attnh, woh, b_o, out, M_ROWS, EMB, EMB);
}